// round 9
// baseline (speedup 1.0000x reference)
#include <cuda_runtime.h>
#include <cuda_bf16.h>
#include <math.h>
#include <stdint.h>

#define NN   100000
#define OC   128
#define MAXE 1600000

// ---------------------------------------------------------------------------
// Device scratch
// ---------------------------------------------------------------------------
__device__ __align__(16) float g_A [(size_t)NN * OC];
__device__ __align__(16) float g_B [(size_t)NN * OC];
__device__ __align__(16) float g_x2[(size_t)NN * OC];
__device__ __align__(16) float g_x4[(size_t)NN * OC];
__device__ __align__(16) float g_x6[(size_t)NN * OC];

__device__ int g_deg[NN];
__device__ int g_off[NN + 1];
__device__ int g_cur[NN];
__device__ int g_ssrc[MAXE];
__device__ int g_sdst[MAXE];
// Pre-packed tf32 B operand per layer: [pair p(8)][kstep(16)][lane(32)] uint4
__device__ __align__(16) uint4 g_wbp[3][4096];
__device__ int g_idx64;

// ---------------------------------------------------------------------------
// tf32 helpers
// ---------------------------------------------------------------------------
__device__ __forceinline__ uint32_t f2tf32(float f) {
    uint32_t r;
    asm("cvt.rna.tf32.f32 %0, %1;" : "=r"(r) : "f"(f));
    return r;
}

__device__ __forceinline__ void mma_tf32(float* d, const uint32_t* a,
                                         uint32_t b0, uint32_t b1) {
    asm volatile(
        "mma.sync.aligned.m16n8k8.row.col.f32.tf32.tf32.f32 "
        "{%0,%1,%2,%3}, {%4,%5,%6,%7}, {%8,%9}, {%0,%1,%2,%3};"
        : "+f"(d[0]), "+f"(d[1]), "+f"(d[2]), "+f"(d[3])
        : "r"(a[0]), "r"(a[1]), "r"(a[2]), "r"(a[3]), "r"(b0), "r"(b1));
}

// ---------------------------------------------------------------------------
// Index-width detection (int32 vs int64 edge_index)
// ---------------------------------------------------------------------------
__global__ void detect_idx_kernel(const int* __restrict__ ei)
{
    __shared__ int any;
    if (threadIdx.x == 0) any = 0;
    __syncthreads();
    for (int i = threadIdx.x; i < 2048; i += blockDim.x)
        if (ei[2 * i + 1] != 0) any = 1;
    __syncthreads();
    if (threadIdx.x == 0) g_idx64 = (any == 0) ? 1 : 0;
}

// ---------------------------------------------------------------------------
// Counting sort by dst
// ---------------------------------------------------------------------------
__global__ void hist_kernel(const void* __restrict__ ei, long long E, int* __restrict__ deg)
{
    const int idx64 = g_idx64;
    long long i = (long long)blockIdx.x * blockDim.x + threadIdx.x;
    const long long stride = (long long)gridDim.x * blockDim.x;
    for (; i < E; i += stride) {
        int d = idx64 ? (int)((const long long*)ei)[E + i] : ((const int*)ei)[E + i];
        atomicAdd(&deg[d], 1);
    }
}

__global__ void scan_kernel(const int* __restrict__ deg, int* __restrict__ off, int n)
{
    __shared__ int sc[1024];
    __shared__ int carry;
    const int tid = threadIdx.x;
    if (tid == 0) carry = 0;
    __syncthreads();
    for (int base = 0; base < n; base += 1024) {
        int i = base + tid;
        int v = (i < n) ? deg[i] : 0;
        sc[tid] = v;
        __syncthreads();
        int run = v;
        for (int d = 1; d < 1024; d <<= 1) {
            int add = (tid >= d) ? sc[tid - d] : 0;
            __syncthreads();
            run += add;
            sc[tid] = run;
            __syncthreads();
        }
        int c = carry;
        if (i < n) off[i] = c + run - v;
        __syncthreads();
        if (tid == 0) carry = c + sc[1023];
        __syncthreads();
    }
    if (tid == 0) off[n] = carry;
}

__global__ void scatter_kernel(const void* __restrict__ ei, long long E,
                               const int* __restrict__ off, int* __restrict__ cur,
                               int* __restrict__ ssrc, int* __restrict__ sdst)
{
    const int idx64 = g_idx64;
    long long i = (long long)blockIdx.x * blockDim.x + threadIdx.x;
    const long long stride = (long long)gridDim.x * blockDim.x;
    for (; i < E; i += stride) {
        int s, d;
        if (idx64) { s = (int)((const long long*)ei)[i]; d = (int)((const long long*)ei)[E + i]; }
        else       { s = ((const int*)ei)[i];            d = ((const int*)ei)[E + i]; }
        int p = off[d] + atomicAdd(&cur[d], 1);
        ssrc[p] = s;
        sdst[p] = d;
    }
}

// ---------------------------------------------------------------------------
// Pack wb [K=128 in][N=128 out] into per-lane tf32 B fragments (m16n8k8).
// ---------------------------------------------------------------------------
__global__ void prep_w_kernel(const float* __restrict__ wb, uint4* __restrict__ outp)
{
    int idx = blockIdx.x * blockDim.x + threadIdx.x;
    if (idx >= 4096) return;
    int lane = idx & 31;
    int kk   = (idx >> 5) & 15;
    int p    = idx >> 9;
    int k0 = kk * 8 + (lane & 3);
    int n0 = p * 16 + (lane >> 2);
    uint4 v;
    v.x = f2tf32(wb[k0 * 128 + n0]);
    v.y = f2tf32(wb[(k0 + 4) * 128 + n0]);
    v.z = f2tf32(wb[k0 * 128 + n0 + 8]);
    v.w = f2tf32(wb[(k0 + 4) * 128 + n0 + 8]);
    outp[idx] = v;
}

// ---------------------------------------------------------------------------
// Node transform: A = x @ (Wtop - Wbot) + ba ;  B = x @ Wbot ; outz = 0
// NPB=16: halves per-layer weight re-read traffic vs NPB=8.
// ---------------------------------------------------------------------------
template<int C, int NPB>
__global__ __launch_bounds__(128)
void node_kernel(const float* __restrict__ x,
                 const float* __restrict__ wa,
                 const float* __restrict__ ba,
                 float* __restrict__ A,
                 float* __restrict__ B,
                 float* __restrict__ outz,
                 int n_nodes)
{
    __shared__ float xs[NPB * C];
    const int n0  = blockIdx.x * NPB;
    const int tid = threadIdx.x;

    for (int i = tid; i < NPB * C; i += 128) {
        int nn = i / C, c = i % C;
        int n = n0 + nn;
        xs[i] = (n < n_nodes) ? x[(size_t)n * C + c] : 0.f;
    }
    __syncthreads();

    float a[NPB], b[NPB];
#pragma unroll
    for (int t = 0; t < NPB; t++) { a[t] = 0.f; b[t] = 0.f; }

    const int o = tid;
#pragma unroll 4
    for (int c = 0; c < C; c++) {
        float wtop = wa[(size_t)c       * OC + o];
        float wbot = wa[(size_t)(C + c) * OC + o];
        float wd   = wtop - wbot;
#pragma unroll
        for (int t = 0; t < NPB; t++) {
            float xv = xs[t * C + c];
            a[t] += xv * wd;
            b[t] += xv * wbot;
        }
    }
    float bao = ba[o];
#pragma unroll
    for (int t = 0; t < NPB; t++) {
        int n = n0 + t;
        if (n < n_nodes) {
            size_t idx = (size_t)n * OC + o;
            A[idx]    = a[t] + bao;
            B[idx]    = b[t];
            outz[idx] = 0.f;
        }
    }
}

// ---------------------------------------------------------------------------
// Edge kernel (mma.sync tf32, sorted edges).
// 3 CTAs/SM: overlapping gather/MMA/epilogue phases across CTAs.
// Weight fragments read from GLOBAL (L1/L2-hot: same 64KB every tile).
// Per 128-edge tile:
//   H[e][k] = tf32(relu(A[dst]+B[src])) -> smem (padded rows)
//   D[128 e][128 out] = H @ Wb via m16n8k8 tf32 mma, warp tile 32x64
//   segmented max over contiguous dst runs + bias; plain store interior,
//   atomicMax(int-bits) on tile-boundary segments.
// ---------------------------------------------------------------------------
#define HP 132  // padded row stride (floats) for H / msg

#define SM_H     0                          // 128*132*4 = 67584
#define SM_SDST  67584                      // int[128]
#define SM_SSRC  (SM_SDST + 512)            // int[128]
#define SM_SEGS  (SM_SSRC + 512)            // int[136]
#define SM_SEGN  (SM_SEGS + 544)            // int[128]
#define SM_BB    (SM_SEGN + 512)            // float[128]
#define SM_WC    (SM_BB + 512)              // int[8]
#define SM_NSEG  (SM_WC + 32)               // int[4]
#define SM_TOTAL (SM_NSEG + 16)             // 70240  (< 227K/3 = 75.7K)

__global__ __launch_bounds__(256, 3)
void edge_mma_kernel(const float4* __restrict__ nodeA,
                     const float4* __restrict__ nodeB,
                     const int* __restrict__ ssrc_g,
                     const int* __restrict__ sdst_g,
                     const uint4* __restrict__ wbp,
                     const float* __restrict__ bb,
                     float* __restrict__ out,
                     int E)
{
    extern __shared__ __align__(16) char smem[];
    const int tid  = threadIdx.x;
    const int wid  = tid >> 5;
    const int lane = tid & 31;
    const unsigned FULL = 0xffffffffu;

    uint32_t* Hs   = (uint32_t*)(smem + SM_H);
    float*    msg  = (float*)(smem + SM_H);      // same region, after MMA
    int*      sdst = (int*)(smem + SM_SDST);
    int*      ssrc = (int*)(smem + SM_SSRC);
    int*      segs = (int*)(smem + SM_SEGS);
    int*      segn = (int*)(smem + SM_SEGN);
    float*    bbs  = (float*)(smem + SM_BB);
    int*      swc  = (int*)(smem + SM_WC);
    int*      snseg= (int*)(smem + SM_NSEG);

    if (tid < 128) bbs[tid] = bb[tid];

    const int ntiles = (E + 127) >> 7;
    const int wM = wid & 3;      // edge-stripe  [wM*32, +32)
    const int wN = wid >> 2;     // out-half     [wN*64, +64)

    for (int t = blockIdx.x; t < ntiles; t += gridDim.x) {
        const int e0  = t << 7;
        const int cnt = min(128, E - e0);

        if (tid < 128) {
            sdst[tid] = (tid < cnt) ? sdst_g[e0 + tid] : -1;
            ssrc[tid] = (tid < cnt) ? ssrc_g[e0 + tid] : 0;
        }
        __syncthreads();

        // ---- segment heads (warps 0..3) ----
        int head = 0; unsigned bm = 0;
        if (tid < 128) {
            head = (tid < cnt) && (tid == 0 || sdst[tid] != sdst[tid - 1]);
            bm = __ballot_sync(FULL, head);
            if (lane == 0) swc[wid] = __popc(bm);
        }
        __syncthreads();
        if (tid == 0) {
            int s = 0;
            for (int w = 0; w < 4; w++) { swc[4 + w] = s; s += swc[w]; }
            snseg[0] = s;
            segs[s]  = cnt;
        }
        __syncthreads();
        if (head) {
            int sid = swc[4 + wid] + __popc(bm & ((1u << lane) - 1u));
            segs[sid] = tid;
            segn[sid] = sdst[tid];
        }

        // ---- gather: H[e][k] = tf32(relu(A[dst]+B[src])) ----
        {
            const int e    = tid >> 1;
            const int half = tid & 1;
            uint32_t* hr = Hs + e * HP + half * 64;
            if (e < cnt) {
                const size_t dr = (size_t)sdst[e] * 32 + half * 16;
                const size_t sr = (size_t)ssrc[e] * 32 + half * 16;
#pragma unroll
                for (int j = 0; j < 16; j++) {
                    float4 av = nodeA[dr + j];
                    float4 bv = nodeB[sr + j];
                    uint4 hv;
                    hv.x = f2tf32(fmaxf(av.x + bv.x, 0.f));
                    hv.y = f2tf32(fmaxf(av.y + bv.y, 0.f));
                    hv.z = f2tf32(fmaxf(av.z + bv.z, 0.f));
                    hv.w = f2tf32(fmaxf(av.w + bv.w, 0.f));
                    *(uint4*)(hr + j * 4) = hv;
                }
            } else {
#pragma unroll
                for (int j = 0; j < 16; j++)
                    *(uint4*)(hr + j * 4) = make_uint4(0u, 0u, 0u, 0u);
            }
        }
        __syncthreads();

        // ---- MMA: warp tile 32 edges x 64 outs; W from global (L1-hot) ----
        float acc[2][8][4];
#pragma unroll
        for (int mt = 0; mt < 2; mt++)
#pragma unroll
            for (int nt = 0; nt < 8; nt++)
#pragma unroll
                for (int r = 0; r < 4; r++) acc[mt][nt][r] = 0.f;

        const int g = lane >> 2, th = lane & 3;
        const uint4* wrow = wbp + (size_t)wN * 2048 + lane;
#pragma unroll 4
        for (int kk = 0; kk < 16; kk++) {
            uint32_t a[2][4];
#pragma unroll
            for (int mt = 0; mt < 2; mt++) {
                const uint32_t* base = Hs + (wM * 32 + mt * 16 + g) * HP + kk * 8 + th;
                a[mt][0] = base[0];
                a[mt][1] = base[8 * HP];
                a[mt][2] = base[4];
                a[mt][3] = base[8 * HP + 4];
            }
#pragma unroll
            for (int p = 0; p < 4; p++) {
                uint4 bp = wrow[(p * 16 + kk) * 32];
#pragma unroll
                for (int mt = 0; mt < 2; mt++) {
                    mma_tf32(acc[mt][2 * p],     a[mt], bp.x, bp.y);
                    mma_tf32(acc[mt][2 * p + 1], a[mt], bp.z, bp.w);
                }
            }
        }
        __syncthreads();   // all warps done reading H

        // ---- store D -> msg[e][c] ----
#pragma unroll
        for (int mt = 0; mt < 2; mt++) {
            const int row = wM * 32 + mt * 16 + g;
#pragma unroll
            for (int nt = 0; nt < 8; nt++) {
                const int col = wN * 64 + nt * 8 + 2 * th;
                *(float2*)(msg + row * HP + col) =
                    make_float2(acc[mt][nt][0], acc[mt][nt][1]);
                *(float2*)(msg + (row + 8) * HP + col) =
                    make_float2(acc[mt][nt][2], acc[mt][nt][3]);
            }
        }
        __syncthreads();

        // ---- segmented max + writeback ----
        {
            const int nseg = snseg[0];
            for (int i = tid; i < nseg * 128; i += 256) {
                const int c = i & 127;
                const int s = i >> 7;
                const int st = segs[s], en = segs[s + 1];
                float m = -3.4e38f;
                for (int e = st; e < en; e++)
                    m = fmaxf(m, msg[e * HP + c]);
                m += bbs[c];
                float* o = out + (size_t)segn[s] * OC + c;
                if (st == 0 || en == cnt) {
                    atomicMax((int*)o, __float_as_int(m));  // 0-init => relu free
                } else {
                    *o = fmaxf(m, 0.f);                     // sole writer
                }
            }
        }
        __syncthreads();
    }
}

// ---------------------------------------------------------------------------
// Final: concat(x2,x4,x6) [384] -> maxpool(24) -> 16 -> @ fw + fb
// ---------------------------------------------------------------------------
__global__ __launch_bounds__(256)
void final_kernel(const float* __restrict__ x2,
                  const float* __restrict__ x4,
                  const float* __restrict__ x6,
                  const float* __restrict__ fw,
                  const float* __restrict__ fb,
                  float* __restrict__ out,
                  int n_nodes)
{
    const unsigned FULL = 0xffffffffu;
    const int lane = threadIdx.x & 31;
    const int warp = blockIdx.x * (blockDim.x >> 5) + (threadIdx.x >> 5);
    const int nw   = gridDim.x * (blockDim.x >> 5);

    for (int n = warp; n < n_nodes; n += nw) {
        float m = -3.4e38f;
        int idx0 = lane * 12;
#pragma unroll
        for (int i = 0; i < 12; i++) {
            int idx = idx0 + i;
            float v;
            if (idx < 128)       v = x2[(size_t)n * OC + idx];
            else if (idx < 256)  v = x4[(size_t)n * OC + idx - 128];
            else                 v = x6[(size_t)n * OC + idx - 256];
            m = fmaxf(m, v);
        }
        float mm = fmaxf(m, __shfl_xor_sync(FULL, m, 1));
        float part = ((lane & 1) == 0) ? mm * fw[lane >> 1] : 0.f;
#pragma unroll
        for (int off = 16; off >= 1; off >>= 1)
            part += __shfl_xor_sync(FULL, part, off);
        if (lane == 0) out[n] = part + fb[0];
    }
}

// ---------------------------------------------------------------------------
extern "C" void kernel_launch(void* const* d_in, const int* in_sizes, int n_in,
                              void* d_out, int out_size)
{
    const float* x   = (const float*)d_in[0];
    const void*  ei  = d_in[1];
    const float* w1a = (const float*)d_in[2];  const float* b1a = (const float*)d_in[3];
    const float* w1b = (const float*)d_in[4];  const float* b1b = (const float*)d_in[5];
    const float* w2a = (const float*)d_in[6];  const float* b2a = (const float*)d_in[7];
    const float* w2b = (const float*)d_in[8];  const float* b2b = (const float*)d_in[9];
    const float* w3a = (const float*)d_in[10]; const float* b3a = (const float*)d_in[11];
    const float* w3b = (const float*)d_in[12]; const float* b3b = (const float*)d_in[13];
    const float* fw  = (const float*)d_in[14]; const float* fb  = (const float*)d_in[15];
    float* out = (float*)d_out;

    const int       N = in_sizes[0] / 24;
    const long long E = in_sizes[1] / 2;

    float *A, *B, *X2, *X4, *X6;
    int *deg, *off, *cur, *ssrc, *sdst;
    uint4 *wbp;
    cudaGetSymbolAddress((void**)&A,    g_A);
    cudaGetSymbolAddress((void**)&B,    g_B);
    cudaGetSymbolAddress((void**)&X2,   g_x2);
    cudaGetSymbolAddress((void**)&X4,   g_x4);
    cudaGetSymbolAddress((void**)&X6,   g_x6);
    cudaGetSymbolAddress((void**)&deg,  g_deg);
    cudaGetSymbolAddress((void**)&off,  g_off);
    cudaGetSymbolAddress((void**)&cur,  g_cur);
    cudaGetSymbolAddress((void**)&ssrc, g_ssrc);
    cudaGetSymbolAddress((void**)&sdst, g_sdst);
    cudaGetSymbolAddress((void**)&wbp,  g_wbp);

    cudaFuncSetAttribute(edge_mma_kernel,
                         cudaFuncAttributeMaxDynamicSharedMemorySize, SM_TOTAL);

    // ---- edge-index width + counting sort by dst ----
    detect_idx_kernel<<<1, 256>>>((const int*)ei);
    cudaMemsetAsync(deg, 0, (size_t)N * sizeof(int));
    cudaMemsetAsync(cur, 0, (size_t)N * sizeof(int));
    hist_kernel<<<512, 256>>>(ei, E, deg);
    scan_kernel<<<1, 1024>>>(deg, off, N);
    scatter_kernel<<<512, 256>>>(ei, E, off, cur, ssrc, sdst);

    // ---- weight prep (tf32 packed B fragments) ----
    prep_w_kernel<<<16, 256>>>(w1b, wbp);
    prep_w_kernel<<<16, 256>>>(w2b, wbp + 4096);
    prep_w_kernel<<<16, 256>>>(w3b, wbp + 8192);

    const int NPB = 16;
    const int node_grid = (N + NPB - 1) / NPB;
    const int edge_grid = 444;   // 3 CTAs/SM

    // Layer 1 (C = 24)
    node_kernel<24, 16><<<node_grid, 128>>>(x, w1a, b1a, A, B, X2, N);
    edge_mma_kernel<<<edge_grid, 256, SM_TOTAL>>>((const float4*)A, (const float4*)B,
        ssrc, sdst, wbp, b1b, X2, (int)E);
    // Layer 2 (C = 128)
    node_kernel<128, 16><<<node_grid, 128>>>(X2, w2a, b2a, A, B, X4, N);
    edge_mma_kernel<<<edge_grid, 256, SM_TOTAL>>>((const float4*)A, (const float4*)B,
        ssrc, sdst, wbp + 4096, b2b, X4, (int)E);
    // Layer 3 (C = 128)
    node_kernel<128, 16><<<node_grid, 128>>>(X4, w3a, b3a, A, B, X6, N);
    edge_mma_kernel<<<edge_grid, 256, SM_TOTAL>>>((const float4*)A, (const float4*)B,
        ssrc, sdst, wbp + 8192, b3b, X6, (int)E);

    // Pool + final linear
    final_kernel<<<(N + 7) / 8, 256>>>(X2, X4, X6, fw, fb, out, N);
}

// round 10
// speedup vs baseline: 1.8467x; 1.8467x over previous
#include <cuda_runtime.h>
#include <cuda_fp16.h>
#include <math.h>
#include <stdint.h>

#define NN   100000
#define OC   128
#define MAXE 1600000

// ---------------------------------------------------------------------------
// Device scratch
// ---------------------------------------------------------------------------
__device__ __align__(16) float g_A [(size_t)NN * OC];
__device__ __align__(16) float g_B [(size_t)NN * OC];
__device__ __align__(16) float g_x2[(size_t)NN * OC];
__device__ __align__(16) float g_x4[(size_t)NN * OC];
__device__ __align__(16) float g_x6[(size_t)NN * OC];

__device__ int g_deg[NN];
__device__ int g_off[NN + 1];
__device__ int g_cur[NN];
__device__ int g_ssrc[MAXE];
__device__ int g_sdst[MAXE];
// Packed fp16 B fragments per layer: [wN(2)][kk(8)][p(4)][lane(32)] uint4
//   uint4 = { b0(nt=2p), b1(nt=2p), b0(nt=2p+1), b1(nt=2p+1) }  (f16x2 each)
__device__ __align__(16) uint4 g_wbph[3][2048];
__device__ int g_idx64;

// ---------------------------------------------------------------------------
// helpers
// ---------------------------------------------------------------------------
__device__ __forceinline__ uint32_t pack_h2(float lo, float hi) {
    __half2 h = __floats2half2_rn(lo, hi);
    return *(uint32_t*)&h;
}

__device__ __forceinline__ void mma_f16(float* d, const uint32_t* a,
                                        uint32_t b0, uint32_t b1) {
    asm volatile(
        "mma.sync.aligned.m16n8k16.row.col.f32.f16.f16.f32 "
        "{%0,%1,%2,%3}, {%4,%5,%6,%7}, {%8,%9}, {%0,%1,%2,%3};"
        : "+f"(d[0]), "+f"(d[1]), "+f"(d[2]), "+f"(d[3])
        : "r"(a[0]), "r"(a[1]), "r"(a[2]), "r"(a[3]), "r"(b0), "r"(b1));
}

// ---------------------------------------------------------------------------
// Index-width detection (int32 vs int64 edge_index)
// ---------------------------------------------------------------------------
__global__ void detect_idx_kernel(const int* __restrict__ ei)
{
    __shared__ int any;
    if (threadIdx.x == 0) any = 0;
    __syncthreads();
    for (int i = threadIdx.x; i < 2048; i += blockDim.x)
        if (ei[2 * i + 1] != 0) any = 1;
    __syncthreads();
    if (threadIdx.x == 0) g_idx64 = (any == 0) ? 1 : 0;
}

// ---------------------------------------------------------------------------
// Counting sort by dst
// ---------------------------------------------------------------------------
__global__ void hist_kernel(const void* __restrict__ ei, long long E, int* __restrict__ deg)
{
    const int idx64 = g_idx64;
    long long i = (long long)blockIdx.x * blockDim.x + threadIdx.x;
    const long long stride = (long long)gridDim.x * blockDim.x;
    for (; i < E; i += stride) {
        int d = idx64 ? (int)((const long long*)ei)[E + i] : ((const int*)ei)[E + i];
        atomicAdd(&deg[d], 1);
    }
}

__global__ void scan_kernel(const int* __restrict__ deg, int* __restrict__ off, int n)
{
    __shared__ int sc[1024];
    __shared__ int carry;
    const int tid = threadIdx.x;
    if (tid == 0) carry = 0;
    __syncthreads();
    for (int base = 0; base < n; base += 1024) {
        int i = base + tid;
        int v = (i < n) ? deg[i] : 0;
        sc[tid] = v;
        __syncthreads();
        int run = v;
        for (int d = 1; d < 1024; d <<= 1) {
            int add = (tid >= d) ? sc[tid - d] : 0;
            __syncthreads();
            run += add;
            sc[tid] = run;
            __syncthreads();
        }
        int c = carry;
        if (i < n) off[i] = c + run - v;
        __syncthreads();
        if (tid == 0) carry = c + sc[1023];
        __syncthreads();
    }
    if (tid == 0) off[n] = carry;
}

__global__ void scatter_kernel(const void* __restrict__ ei, long long E,
                               const int* __restrict__ off, int* __restrict__ cur,
                               int* __restrict__ ssrc, int* __restrict__ sdst)
{
    const int idx64 = g_idx64;
    long long i = (long long)blockIdx.x * blockDim.x + threadIdx.x;
    const long long stride = (long long)gridDim.x * blockDim.x;
    for (; i < E; i += stride) {
        int s, d;
        if (idx64) { s = (int)((const long long*)ei)[i]; d = (int)((const long long*)ei)[E + i]; }
        else       { s = ((const int*)ei)[i];            d = ((const int*)ei)[E + i]; }
        int p = off[d] + atomicAdd(&cur[d], 1);
        ssrc[p] = s;
        sdst[p] = d;
    }
}

// ---------------------------------------------------------------------------
// Pack wb [K=128 in][N=128 out] into fp16 B fragments for m16n8k16 (col-major B):
//   b0: k = kk*16 + 2*th {+0,1}, n = base + g ;  b1: same with k+8
// ---------------------------------------------------------------------------
__global__ void prep_wh_kernel(const float* __restrict__ wb, uint4* __restrict__ outp)
{
    int idx = blockIdx.x * blockDim.x + threadIdx.x;
    if (idx >= 2048) return;
    int lane = idx & 31;
    int p    = (idx >> 5) & 3;
    int kk   = (idx >> 7) & 7;
    int wN   = idx >> 10;
    int g  = lane >> 2, th = lane & 3;
    int n0 = wN * 64 + p * 16 + g;   // nt0 = 2p
    int n1 = n0 + 8;                 // nt1 = 2p+1
    int k0 = kk * 16 + 2 * th;
    uint4 v;
    v.x = pack_h2(wb[k0 * 128 + n0],       wb[(k0 + 1) * 128 + n0]);
    v.y = pack_h2(wb[(k0 + 8) * 128 + n0], wb[(k0 + 9) * 128 + n0]);
    v.z = pack_h2(wb[k0 * 128 + n1],       wb[(k0 + 1) * 128 + n1]);
    v.w = pack_h2(wb[(k0 + 8) * 128 + n1], wb[(k0 + 9) * 128 + n1]);
    outp[idx] = v;
}

// ---------------------------------------------------------------------------
// Node transform: A = x @ (Wtop - Wbot) + ba ;  B = x @ Wbot ; outz = 0
// ---------------------------------------------------------------------------
template<int C, int NPB>
__global__ __launch_bounds__(128)
void node_kernel(const float* __restrict__ x,
                 const float* __restrict__ wa,
                 const float* __restrict__ ba,
                 float* __restrict__ A,
                 float* __restrict__ B,
                 float* __restrict__ outz,
                 int n_nodes)
{
    __shared__ float xs[NPB * C];
    const int n0  = blockIdx.x * NPB;
    const int tid = threadIdx.x;

    for (int i = tid; i < NPB * C; i += 128) {
        int nn = i / C, c = i % C;
        int n = n0 + nn;
        xs[i] = (n < n_nodes) ? x[(size_t)n * C + c] : 0.f;
    }
    __syncthreads();

    float a[NPB], b[NPB];
#pragma unroll
    for (int t = 0; t < NPB; t++) { a[t] = 0.f; b[t] = 0.f; }

    const int o = tid;
#pragma unroll 4
    for (int c = 0; c < C; c++) {
        float wtop = wa[(size_t)c       * OC + o];
        float wbot = wa[(size_t)(C + c) * OC + o];
        float wd   = wtop - wbot;
#pragma unroll
        for (int t = 0; t < NPB; t++) {
            float xv = xs[t * C + c];
            a[t] += xv * wd;
            b[t] += xv * wbot;
        }
    }
    float bao = ba[o];
#pragma unroll
    for (int t = 0; t < NPB; t++) {
        int n = n0 + t;
        if (n < n_nodes) {
            size_t idx = (size_t)n * OC + o;
            A[idx]    = a[t] + bao;
            B[idx]    = b[t];
            outz[idx] = 0.f;
        }
    }
}

// ---------------------------------------------------------------------------
// Edge kernel (mma.sync fp16 m16n8k16, sorted edges, 2 CTAs/SM).
// Per 128-edge tile:
//   H[e][k] = fp16(relu(A[dst]+B[src])) -> smem (68-word padded rows)
//   D[128 e][128 out] = H @ Wb via m16n8k16, warp tile 32x64, fp32 accum
//   segmented max over contiguous dst runs + bias; plain store interior,
//   atomicMax(int-bits) on tile-boundary segments.
// ---------------------------------------------------------------------------
#define HP  132   // msg row stride (fp32 words)
#define HHW 68    // H row stride in 32-bit words (= 136 fp16)

#define SM_H     0                          // max(H 34816B, msg 67584B) = 67584
#define SM_SDST  67584                      // int[128]
#define SM_SSRC  (SM_SDST + 512)            // int[128]
#define SM_SEGS  (SM_SSRC + 512)            // int[136]
#define SM_SEGN  (SM_SEGS + 544)            // int[128]
#define SM_BB    (SM_SEGN + 512)            // float[128]
#define SM_WC    (SM_BB + 512)              // int[8]
#define SM_NSEG  (SM_WC + 32)               // int[4]
#define SM_TOTAL (SM_NSEG + 16)             // 70240

__global__ __launch_bounds__(256, 2)
void edge_mma_kernel(const float4* __restrict__ nodeA,
                     const float4* __restrict__ nodeB,
                     const int* __restrict__ ssrc_g,
                     const int* __restrict__ sdst_g,
                     const uint4* __restrict__ wbph,
                     const float* __restrict__ bb,
                     float* __restrict__ out,
                     int E)
{
    extern __shared__ __align__(16) char smem[];
    const int tid  = threadIdx.x;
    const int wid  = tid >> 5;
    const int lane = tid & 31;
    const unsigned FULL = 0xffffffffu;

    uint32_t* Hw   = (uint32_t*)(smem + SM_H);   // fp16x2 words
    float*    msg  = (float*)(smem + SM_H);      // same region, after MMA
    int*      sdst = (int*)(smem + SM_SDST);
    int*      ssrc = (int*)(smem + SM_SSRC);
    int*      segs = (int*)(smem + SM_SEGS);
    int*      segn = (int*)(smem + SM_SEGN);
    float*    bbs  = (float*)(smem + SM_BB);
    int*      swc  = (int*)(smem + SM_WC);
    int*      snseg= (int*)(smem + SM_NSEG);

    if (tid < 128) bbs[tid] = bb[tid];

    const int ntiles = (E + 127) >> 7;
    const int wM = wid & 3;      // edge-stripe  [wM*32, +32)
    const int wN = wid >> 2;     // out-half     [wN*64, +64)

    for (int t = blockIdx.x; t < ntiles; t += gridDim.x) {
        const int e0  = t << 7;
        const int cnt = min(128, E - e0);

        if (tid < 128) {
            sdst[tid] = (tid < cnt) ? sdst_g[e0 + tid] : -1;
            ssrc[tid] = (tid < cnt) ? ssrc_g[e0 + tid] : 0;
        }
        __syncthreads();

        // ---- segment heads (warps 0..3) ----
        int head = 0; unsigned bm = 0;
        if (tid < 128) {
            head = (tid < cnt) && (tid == 0 || sdst[tid] != sdst[tid - 1]);
            bm = __ballot_sync(FULL, head);
            if (lane == 0) swc[wid] = __popc(bm);
        }
        __syncthreads();
        if (tid == 0) {
            int s = 0;
            for (int w = 0; w < 4; w++) { swc[4 + w] = s; s += swc[w]; }
            snseg[0] = s;
            segs[s]  = cnt;
        }
        __syncthreads();
        if (head) {
            int sid = swc[4 + wid] + __popc(bm & ((1u << lane) - 1u));
            segs[sid] = tid;
            segn[sid] = sdst[tid];
        }

        // ---- gather: H[e][k] = fp16(relu(A[dst]+B[src])) ----
        {
            const int e    = tid >> 1;
            const int half = tid & 1;
            uint4* hrow = (uint4*)Hw + (e * HHW + half * 32) / 4;  // e*17 + half*8
            if (e < cnt) {
                const size_t dr = (size_t)sdst[e] * 32 + half * 16;
                const size_t sr = (size_t)ssrc[e] * 32 + half * 16;
#pragma unroll
                for (int m = 0; m < 8; m++) {
                    float4 a0 = nodeA[dr + 2 * m];
                    float4 b0 = nodeB[sr + 2 * m];
                    float4 a1 = nodeA[dr + 2 * m + 1];
                    float4 b1 = nodeB[sr + 2 * m + 1];
                    uint4 w;
                    w.x = pack_h2(fmaxf(a0.x + b0.x, 0.f), fmaxf(a0.y + b0.y, 0.f));
                    w.y = pack_h2(fmaxf(a0.z + b0.z, 0.f), fmaxf(a0.w + b0.w, 0.f));
                    w.z = pack_h2(fmaxf(a1.x + b1.x, 0.f), fmaxf(a1.y + b1.y, 0.f));
                    w.w = pack_h2(fmaxf(a1.z + b1.z, 0.f), fmaxf(a1.w + b1.w, 0.f));
                    hrow[m] = w;
                }
            } else {
#pragma unroll
                for (int m = 0; m < 8; m++)
                    hrow[m] = make_uint4(0u, 0u, 0u, 0u);
            }
        }
        __syncthreads();

        // ---- MMA: warp tile 32 edges x 64 outs, m16n8k16 fp16 ----
        float acc[2][8][4];
#pragma unroll
        for (int mt = 0; mt < 2; mt++)
#pragma unroll
            for (int nt = 0; nt < 8; nt++)
#pragma unroll
                for (int r = 0; r < 4; r++) acc[mt][nt][r] = 0.f;

        const int g = lane >> 2, th = lane & 3;
        const uint4* wrow = wbph + (size_t)wN * 1024 + lane;
#pragma unroll
        for (int kk = 0; kk < 8; kk++) {
            uint32_t a[2][4];
#pragma unroll
            for (int mt = 0; mt < 2; mt++) {
                const uint32_t* base = Hw + (wM * 32 + mt * 16 + g) * HHW + kk * 8 + th;
                a[mt][0] = base[0];            // row g,   k pair 2th
                a[mt][1] = base[8 * HHW];      // row g+8, k pair 2th
                a[mt][2] = base[4];            // row g,   k pair 2th+8
                a[mt][3] = base[8 * HHW + 4];  // row g+8, k pair 2th+8
            }
#pragma unroll
            for (int p = 0; p < 4; p++) {
                uint4 bp = wrow[kk * 128 + p * 32];
#pragma unroll
                for (int mt = 0; mt < 2; mt++) {
                    mma_f16(acc[mt][2 * p],     a[mt], bp.x, bp.y);
                    mma_f16(acc[mt][2 * p + 1], a[mt], bp.z, bp.w);
                }
            }
        }
        __syncthreads();   // all warps done reading H

        // ---- store D -> msg[e][c] (fp32) ----
#pragma unroll
        for (int mt = 0; mt < 2; mt++) {
            const int row = wM * 32 + mt * 16 + g;
#pragma unroll
            for (int nt = 0; nt < 8; nt++) {
                const int col = wN * 64 + nt * 8 + 2 * th;
                *(float2*)(msg + row * HP + col) =
                    make_float2(acc[mt][nt][0], acc[mt][nt][1]);
                *(float2*)(msg + (row + 8) * HP + col) =
                    make_float2(acc[mt][nt][2], acc[mt][nt][3]);
            }
        }
        __syncthreads();

        // ---- segmented max + writeback ----
        {
            const int nseg = snseg[0];
            for (int i = tid; i < nseg * 128; i += 256) {
                const int c = i & 127;
                const int s = i >> 7;
                const int st = segs[s], en = segs[s + 1];
                float m = -3.4e38f;
                for (int e = st; e < en; e++)
                    m = fmaxf(m, msg[e * HP + c]);
                m += bbs[c];
                float* o = out + (size_t)segn[s] * OC + c;
                if (st == 0 || en == cnt) {
                    atomicMax((int*)o, __float_as_int(m));  // 0-init => relu free
                } else {
                    *o = fmaxf(m, 0.f);                     // sole writer
                }
            }
        }
        __syncthreads();
    }
}

// ---------------------------------------------------------------------------
// Final: concat(x2,x4,x6) [384] -> maxpool(24) -> 16 -> @ fw + fb
// ---------------------------------------------------------------------------
__global__ __launch_bounds__(256)
void final_kernel(const float* __restrict__ x2,
                  const float* __restrict__ x4,
                  const float* __restrict__ x6,
                  const float* __restrict__ fw,
                  const float* __restrict__ fb,
                  float* __restrict__ out,
                  int n_nodes)
{
    const unsigned FULL = 0xffffffffu;
    const int lane = threadIdx.x & 31;
    const int warp = blockIdx.x * (blockDim.x >> 5) + (threadIdx.x >> 5);
    const int nw   = gridDim.x * (blockDim.x >> 5);

    for (int n = warp; n < n_nodes; n += nw) {
        float m = -3.4e38f;
        int idx0 = lane * 12;
#pragma unroll
        for (int i = 0; i < 12; i++) {
            int idx = idx0 + i;
            float v;
            if (idx < 128)       v = x2[(size_t)n * OC + idx];
            else if (idx < 256)  v = x4[(size_t)n * OC + idx - 128];
            else                 v = x6[(size_t)n * OC + idx - 256];
            m = fmaxf(m, v);
        }
        float mm = fmaxf(m, __shfl_xor_sync(FULL, m, 1));
        float part = ((lane & 1) == 0) ? mm * fw[lane >> 1] : 0.f;
#pragma unroll
        for (int off = 16; off >= 1; off >>= 1)
            part += __shfl_xor_sync(FULL, part, off);
        if (lane == 0) out[n] = part + fb[0];
    }
}

// ---------------------------------------------------------------------------
extern "C" void kernel_launch(void* const* d_in, const int* in_sizes, int n_in,
                              void* d_out, int out_size)
{
    const float* x   = (const float*)d_in[0];
    const void*  ei  = d_in[1];
    const float* w1a = (const float*)d_in[2];  const float* b1a = (const float*)d_in[3];
    const float* w1b = (const float*)d_in[4];  const float* b1b = (const float*)d_in[5];
    const float* w2a = (const float*)d_in[6];  const float* b2a = (const float*)d_in[7];
    const float* w2b = (const float*)d_in[8];  const float* b2b = (const float*)d_in[9];
    const float* w3a = (const float*)d_in[10]; const float* b3a = (const float*)d_in[11];
    const float* w3b = (const float*)d_in[12]; const float* b3b = (const float*)d_in[13];
    const float* fw  = (const float*)d_in[14]; const float* fb  = (const float*)d_in[15];
    float* out = (float*)d_out;

    const int       N = in_sizes[0] / 24;
    const long long E = in_sizes[1] / 2;

    float *A, *B, *X2, *X4, *X6;
    int *deg, *off, *cur, *ssrc, *sdst;
    uint4 *wbph;
    cudaGetSymbolAddress((void**)&A,    g_A);
    cudaGetSymbolAddress((void**)&B,    g_B);
    cudaGetSymbolAddress((void**)&X2,   g_x2);
    cudaGetSymbolAddress((void**)&X4,   g_x4);
    cudaGetSymbolAddress((void**)&X6,   g_x6);
    cudaGetSymbolAddress((void**)&deg,  g_deg);
    cudaGetSymbolAddress((void**)&off,  g_off);
    cudaGetSymbolAddress((void**)&cur,  g_cur);
    cudaGetSymbolAddress((void**)&ssrc, g_ssrc);
    cudaGetSymbolAddress((void**)&sdst, g_sdst);
    cudaGetSymbolAddress((void**)&wbph, g_wbph);

    cudaFuncSetAttribute(edge_mma_kernel,
                         cudaFuncAttributeMaxDynamicSharedMemorySize, SM_TOTAL);

    // ---- edge-index width + counting sort by dst ----
    detect_idx_kernel<<<1, 256>>>((const int*)ei);
    cudaMemsetAsync(deg, 0, (size_t)N * sizeof(int));
    cudaMemsetAsync(cur, 0, (size_t)N * sizeof(int));
    hist_kernel<<<512, 256>>>(ei, E, deg);
    scan_kernel<<<1, 1024>>>(deg, off, N);
    scatter_kernel<<<512, 256>>>(ei, E, off, cur, ssrc, sdst);

    // ---- weight prep (fp16 packed B fragments) ----
    prep_wh_kernel<<<8, 256>>>(w1b, wbph);
    prep_wh_kernel<<<8, 256>>>(w2b, wbph + 2048);
    prep_wh_kernel<<<8, 256>>>(w3b, wbph + 4096);

    const int NPB = 16;
    const int node_grid = (N + NPB - 1) / NPB;
    const int edge_grid = 296;   // 2 CTAs/SM (proven best in R8)

    // Layer 1 (C = 24)
    node_kernel<24, 16><<<node_grid, 128>>>(x, w1a, b1a, A, B, X2, N);
    edge_mma_kernel<<<edge_grid, 256, SM_TOTAL>>>((const float4*)A, (const float4*)B,
        ssrc, sdst, wbph, b1b, X2, (int)E);
    // Layer 2 (C = 128)
    node_kernel<128, 16><<<node_grid, 128>>>(X2, w2a, b2a, A, B, X4, N);
    edge_mma_kernel<<<edge_grid, 256, SM_TOTAL>>>((const float4*)A, (const float4*)B,
        ssrc, sdst, wbph + 2048, b2b, X4, (int)E);
    // Layer 3 (C = 128)
    node_kernel<128, 16><<<node_grid, 128>>>(X4, w3a, b3a, A, B, X6, N);
    edge_mma_kernel<<<edge_grid, 256, SM_TOTAL>>>((const float4*)A, (const float4*)B,
        ssrc, sdst, wbph + 4096, b3b, X6, (int)E);

    // Pool + final linear
    final_kernel<<<(N + 7) / 8, 256>>>(X2, X4, X6, fw, fb, out, N);
}

// round 11
// speedup vs baseline: 2.1284x; 1.1526x over previous
#include <cuda_runtime.h>
#include <cuda_fp16.h>
#include <math.h>
#include <stdint.h>

#define NN   100000
#define OC   128
#define MAXE 1600000

// ---------------------------------------------------------------------------
// Device scratch
// ---------------------------------------------------------------------------
__device__ __align__(16) float  g_A [(size_t)NN * OC];
__device__ __align__(16) __half g_Bh[(size_t)NN * OC];
__device__ __align__(16) float  g_x2[(size_t)NN * OC];
__device__ __align__(16) float  g_x4[(size_t)NN * OC];
__device__ __align__(16) float  g_x6[(size_t)NN * OC];

__device__ int g_deg[NN];
__device__ int g_off[NN + 1];
__device__ int g_cur[NN];
__device__ int g_ssrc[MAXE];
__device__ int g_sdst[MAXE];
// Packed fp16 B fragments per layer: [wN(2)][kk(8)][p(4)][lane(32)] uint4
__device__ __align__(16) uint4 g_wbph[3][2048];
__device__ int g_idx64;

// ---------------------------------------------------------------------------
// helpers
// ---------------------------------------------------------------------------
__device__ __forceinline__ uint32_t pack_h2(float lo, float hi) {
    __half2 h = __floats2half2_rn(lo, hi);
    return *(uint32_t*)&h;
}

__device__ __forceinline__ void mma_f16(float* d, const uint32_t* a,
                                        uint32_t b0, uint32_t b1) {
    asm volatile(
        "mma.sync.aligned.m16n8k16.row.col.f32.f16.f16.f32 "
        "{%0,%1,%2,%3}, {%4,%5,%6,%7}, {%8,%9}, {%0,%1,%2,%3};"
        : "+f"(d[0]), "+f"(d[1]), "+f"(d[2]), "+f"(d[3])
        : "r"(a[0]), "r"(a[1]), "r"(a[2]), "r"(a[3]), "r"(b0), "r"(b1));
}

__device__ __forceinline__ uint32_t smem_u32(const void* p) {
    uint32_t a;
    asm("{ .reg .u64 t; cvta.to.shared.u64 t, %1; cvt.u32.u64 %0, t; }"
        : "=r"(a) : "l"(p));
    return a;
}

#define LDMATRIX_X4(r0, r1, r2, r3, addr) \
    asm volatile("ldmatrix.sync.aligned.m8n8.x4.shared.b16 {%0,%1,%2,%3}, [%4];" \
                 : "=r"(r0), "=r"(r1), "=r"(r2), "=r"(r3) : "r"(addr))

// ---------------------------------------------------------------------------
// Index-width detection (int32 vs int64 edge_index)
// ---------------------------------------------------------------------------
__global__ void detect_idx_kernel(const int* __restrict__ ei)
{
    __shared__ int any;
    if (threadIdx.x == 0) any = 0;
    __syncthreads();
    for (int i = threadIdx.x; i < 2048; i += blockDim.x)
        if (ei[2 * i + 1] != 0) any = 1;
    __syncthreads();
    if (threadIdx.x == 0) g_idx64 = (any == 0) ? 1 : 0;
}

// ---------------------------------------------------------------------------
// Counting sort by dst
// ---------------------------------------------------------------------------
__global__ void hist_kernel(const void* __restrict__ ei, long long E, int* __restrict__ deg)
{
    const int idx64 = g_idx64;
    long long i = (long long)blockIdx.x * blockDim.x + threadIdx.x;
    const long long stride = (long long)gridDim.x * blockDim.x;
    for (; i < E; i += stride) {
        int d = idx64 ? (int)((const long long*)ei)[E + i] : ((const int*)ei)[E + i];
        atomicAdd(&deg[d], 1);
    }
}

__global__ void scan_kernel(const int* __restrict__ deg, int* __restrict__ off, int n)
{
    __shared__ int sc[1024];
    __shared__ int carry;
    const int tid = threadIdx.x;
    if (tid == 0) carry = 0;
    __syncthreads();
    for (int base = 0; base < n; base += 1024) {
        int i = base + tid;
        int v = (i < n) ? deg[i] : 0;
        sc[tid] = v;
        __syncthreads();
        int run = v;
        for (int d = 1; d < 1024; d <<= 1) {
            int add = (tid >= d) ? sc[tid - d] : 0;
            __syncthreads();
            run += add;
            sc[tid] = run;
            __syncthreads();
        }
        int c = carry;
        if (i < n) off[i] = c + run - v;
        __syncthreads();
        if (tid == 0) carry = c + sc[1023];
        __syncthreads();
    }
    if (tid == 0) off[n] = carry;
}

__global__ void scatter_kernel(const void* __restrict__ ei, long long E,
                               const int* __restrict__ off, int* __restrict__ cur,
                               int* __restrict__ ssrc, int* __restrict__ sdst)
{
    const int idx64 = g_idx64;
    long long i = (long long)blockIdx.x * blockDim.x + threadIdx.x;
    const long long stride = (long long)gridDim.x * blockDim.x;
    for (; i < E; i += stride) {
        int s, d;
        if (idx64) { s = (int)((const long long*)ei)[i]; d = (int)((const long long*)ei)[E + i]; }
        else       { s = ((const int*)ei)[i];            d = ((const int*)ei)[E + i]; }
        int p = off[d] + atomicAdd(&cur[d], 1);
        ssrc[p] = s;
        sdst[p] = d;
    }
}

// ---------------------------------------------------------------------------
// Pack wb [K=128 in][N=128 out] into fp16 B fragments for m16n8k16 (col-major B)
// ---------------------------------------------------------------------------
__global__ void prep_wh_kernel(const float* __restrict__ wb, uint4* __restrict__ outp)
{
    int idx = blockIdx.x * blockDim.x + threadIdx.x;
    if (idx >= 2048) return;
    int lane = idx & 31;
    int p    = (idx >> 5) & 3;
    int kk   = (idx >> 7) & 7;
    int wN   = idx >> 10;
    int g  = lane >> 2, th = lane & 3;
    int n0 = wN * 64 + p * 16 + g;
    int n1 = n0 + 8;
    int k0 = kk * 16 + 2 * th;
    uint4 v;
    v.x = pack_h2(wb[k0 * 128 + n0],       wb[(k0 + 1) * 128 + n0]);
    v.y = pack_h2(wb[(k0 + 8) * 128 + n0], wb[(k0 + 9) * 128 + n0]);
    v.z = pack_h2(wb[k0 * 128 + n1],       wb[(k0 + 1) * 128 + n1]);
    v.w = pack_h2(wb[(k0 + 8) * 128 + n1], wb[(k0 + 9) * 128 + n1]);
    outp[idx] = v;
}

// ---------------------------------------------------------------------------
// Node transform: A = x @ (Wtop - Wbot) + ba (fp32) ;  Bh = fp16(x @ Wbot) ;
// outz = 0
// ---------------------------------------------------------------------------
template<int C, int NPB>
__global__ __launch_bounds__(128)
void node_kernel(const float* __restrict__ x,
                 const float* __restrict__ wa,
                 const float* __restrict__ ba,
                 float* __restrict__ A,
                 __half* __restrict__ Bh,
                 float* __restrict__ outz,
                 int n_nodes)
{
    __shared__ float xs[NPB * C];
    const int n0  = blockIdx.x * NPB;
    const int tid = threadIdx.x;

    for (int i = tid; i < NPB * C; i += 128) {
        int nn = i / C, c = i % C;
        int n = n0 + nn;
        xs[i] = (n < n_nodes) ? x[(size_t)n * C + c] : 0.f;
    }
    __syncthreads();

    float a[NPB], b[NPB];
#pragma unroll
    for (int t = 0; t < NPB; t++) { a[t] = 0.f; b[t] = 0.f; }

    const int o = tid;
#pragma unroll 4
    for (int c = 0; c < C; c++) {
        float wtop = wa[(size_t)c       * OC + o];
        float wbot = wa[(size_t)(C + c) * OC + o];
        float wd   = wtop - wbot;
#pragma unroll
        for (int t = 0; t < NPB; t++) {
            float xv = xs[t * C + c];
            a[t] += xv * wd;
            b[t] += xv * wbot;
        }
    }
    float bao = ba[o];
#pragma unroll
    for (int t = 0; t < NPB; t++) {
        int n = n0 + t;
        if (n < n_nodes) {
            size_t idx = (size_t)n * OC + o;
            A[idx]    = a[t] + bao;
            Bh[idx]   = __float2half(b[t]);
            outz[idx] = 0.f;
        }
    }
}

// ---------------------------------------------------------------------------
// Edge kernel (mma.sync fp16 m16n8k16, sorted edges, 2 CTAs/SM).
//   H[e][k] = fp16(relu(A_f32[dst] + Bh_f16[src])) -> smem
//   A fragments via ldmatrix.x4 ; W fragments from global (L1-hot)
//   segmented max + bias; plain store interior, atomicMax boundaries.
// ---------------------------------------------------------------------------
#define HP  132   // msg row stride (fp32 words)
#define HHW 68    // H row stride in 32-bit words (= 136 fp16, 272 B)

#define SM_H     0                          // max(H 34816B, msg 67584B) = 67584
#define SM_SDST  67584                      // int[128]
#define SM_SSRC  (SM_SDST + 512)            // int[128]
#define SM_SEGS  (SM_SSRC + 512)            // int[136]
#define SM_SEGN  (SM_SEGS + 544)            // int[128]
#define SM_BB    (SM_SEGN + 512)            // float[128]
#define SM_WC    (SM_BB + 512)              // int[8]
#define SM_NSEG  (SM_WC + 32)               // int[4]
#define SM_TOTAL (SM_NSEG + 16)             // 70240

__global__ __launch_bounds__(256, 2)
void edge_mma_kernel(const float4* __restrict__ nodeA,
                     const uint4*  __restrict__ nodeBh,   // fp16 rows, 16 uint4/row
                     const int* __restrict__ ssrc_g,
                     const int* __restrict__ sdst_g,
                     const uint4* __restrict__ wbph,
                     const float* __restrict__ bb,
                     float* __restrict__ out,
                     int E)
{
    extern __shared__ __align__(16) char smem[];
    const int tid  = threadIdx.x;
    const int wid  = tid >> 5;
    const int lane = tid & 31;
    const unsigned FULL = 0xffffffffu;

    uint32_t* Hw   = (uint32_t*)(smem + SM_H);   // fp16x2 words
    float*    msg  = (float*)(smem + SM_H);      // same region, after MMA
    int*      sdst = (int*)(smem + SM_SDST);
    int*      ssrc = (int*)(smem + SM_SSRC);
    int*      segs = (int*)(smem + SM_SEGS);
    int*      segn = (int*)(smem + SM_SEGN);
    float*    bbs  = (float*)(smem + SM_BB);
    int*      swc  = (int*)(smem + SM_WC);
    int*      snseg= (int*)(smem + SM_NSEG);

    if (tid < 128) bbs[tid] = bb[tid];

    const int ntiles = (E + 127) >> 7;
    const int wM = wid & 3;      // edge-stripe  [wM*32, +32)
    const int wN = wid >> 2;     // out-half     [wN*64, +64)

    // ldmatrix source addresses: lane i -> matrix i>>3, row i&7
    // m0: rows+0 k+0 ; m1: rows+8 k+0 ; m2: rows+0 k+8 ; m3: rows+8 k+8
    const int lm_m   = lane >> 3;
    const int lm_row = (lane & 7) + ((lm_m & 1) << 3);
    const int lm_cw  = (lm_m >> 1) * 4;               // +4 words for k+8
    uint32_t lm_addr[2];
#pragma unroll
    for (int mt = 0; mt < 2; mt++)
        lm_addr[mt] = smem_u32(Hw + (wM * 32 + mt * 16 + lm_row) * HHW + lm_cw);

    for (int t = blockIdx.x; t < ntiles; t += gridDim.x) {
        const int e0  = t << 7;
        const int cnt = min(128, E - e0);

        if (tid < 128) {
            sdst[tid] = (tid < cnt) ? sdst_g[e0 + tid] : -1;
            ssrc[tid] = (tid < cnt) ? ssrc_g[e0 + tid] : 0;
        }
        __syncthreads();

        // ---- segment heads (warps 0..3) ----
        int head = 0; unsigned bm = 0;
        if (tid < 128) {
            head = (tid < cnt) && (tid == 0 || sdst[tid] != sdst[tid - 1]);
            bm = __ballot_sync(FULL, head);
            if (lane == 0) swc[wid] = __popc(bm);
        }
        __syncthreads();
        if (tid == 0) {
            int s = 0;
            for (int w = 0; w < 4; w++) { swc[4 + w] = s; s += swc[w]; }
            snseg[0] = s;
            segs[s]  = cnt;
        }
        __syncthreads();
        if (head) {
            int sid = swc[4 + wid] + __popc(bm & ((1u << lane) - 1u));
            segs[sid] = tid;
            segn[sid] = sdst[tid];
        }

        // ---- gather: H[e][k] = fp16(relu(A_f32[dst] + Bh[src])) ----
        {
            const int e    = tid >> 1;
            const int half = tid & 1;
            uint4* hrow = (uint4*)Hw + e * (HHW / 4) + half * 8;  // e*17 + half*8
            if (e < cnt) {
                const float4* arow = nodeA  + (size_t)sdst[e] * 32 + half * 16;
                const uint4*  brow = nodeBh + (size_t)ssrc[e] * 16 + half * 8;
#pragma unroll
                for (int m = 0; m < 8; m++) {
                    float4 a0 = arow[2 * m];
                    float4 a1 = arow[2 * m + 1];
                    uint4  bv = brow[m];
                    float2 f0 = __half22float2(*(__half2*)&bv.x);
                    float2 f1 = __half22float2(*(__half2*)&bv.y);
                    float2 f2 = __half22float2(*(__half2*)&bv.z);
                    float2 f3 = __half22float2(*(__half2*)&bv.w);
                    uint4 w;
                    w.x = pack_h2(fmaxf(a0.x + f0.x, 0.f), fmaxf(a0.y + f0.y, 0.f));
                    w.y = pack_h2(fmaxf(a0.z + f1.x, 0.f), fmaxf(a0.w + f1.y, 0.f));
                    w.z = pack_h2(fmaxf(a1.x + f2.x, 0.f), fmaxf(a1.y + f2.y, 0.f));
                    w.w = pack_h2(fmaxf(a1.z + f3.x, 0.f), fmaxf(a1.w + f3.y, 0.f));
                    hrow[m] = w;
                }
            } else {
#pragma unroll
                for (int m = 0; m < 8; m++)
                    hrow[m] = make_uint4(0u, 0u, 0u, 0u);
            }
        }
        __syncthreads();

        // ---- MMA: warp tile 32 edges x 64 outs, m16n8k16 fp16 ----
        float acc[2][8][4];
#pragma unroll
        for (int mt = 0; mt < 2; mt++)
#pragma unroll
            for (int nt = 0; nt < 8; nt++)
#pragma unroll
                for (int r = 0; r < 4; r++) acc[mt][nt][r] = 0.f;

        const int g = lane >> 2, th = lane & 3;
        const uint4* wrow = wbph + (size_t)wN * 1024 + lane;
#pragma unroll
        for (int kk = 0; kk < 8; kk++) {
            uint32_t a[2][4];
#pragma unroll
            for (int mt = 0; mt < 2; mt++)
                LDMATRIX_X4(a[mt][0], a[mt][1], a[mt][2], a[mt][3],
                            lm_addr[mt] + kk * 32);
#pragma unroll
            for (int p = 0; p < 4; p++) {
                uint4 bp = wrow[kk * 128 + p * 32];
#pragma unroll
                for (int mt = 0; mt < 2; mt++) {
                    mma_f16(acc[mt][2 * p],     a[mt], bp.x, bp.y);
                    mma_f16(acc[mt][2 * p + 1], a[mt], bp.z, bp.w);
                }
            }
        }
        __syncthreads();   // all warps done reading H

        // ---- store D -> msg[e][c] (fp32) ----
#pragma unroll
        for (int mt = 0; mt < 2; mt++) {
            const int row = wM * 32 + mt * 16 + g;
#pragma unroll
            for (int nt = 0; nt < 8; nt++) {
                const int col = wN * 64 + nt * 8 + 2 * th;
                *(float2*)(msg + row * HP + col) =
                    make_float2(acc[mt][nt][0], acc[mt][nt][1]);
                *(float2*)(msg + (row + 8) * HP + col) =
                    make_float2(acc[mt][nt][2], acc[mt][nt][3]);
            }
        }
        __syncthreads();

        // ---- segmented max + writeback ----
        {
            const int nseg = snseg[0];
            for (int i = tid; i < nseg * 128; i += 256) {
                const int c = i & 127;
                const int s = i >> 7;
                const int st = segs[s], en = segs[s + 1];
                float m = -3.4e38f;
                for (int e = st; e < en; e++)
                    m = fmaxf(m, msg[e * HP + c]);
                m += bbs[c];
                float* o = out + (size_t)segn[s] * OC + c;
                if (st == 0 || en == cnt) {
                    atomicMax((int*)o, __float_as_int(m));  // 0-init => relu free
                } else {
                    *o = fmaxf(m, 0.f);                     // sole writer
                }
            }
        }
        __syncthreads();
    }
}

// ---------------------------------------------------------------------------
// Final: concat(x2,x4,x6) [384] -> maxpool(24) -> 16 -> @ fw + fb
// ---------------------------------------------------------------------------
__global__ __launch_bounds__(256)
void final_kernel(const float* __restrict__ x2,
                  const float* __restrict__ x4,
                  const float* __restrict__ x6,
                  const float* __restrict__ fw,
                  const float* __restrict__ fb,
                  float* __restrict__ out,
                  int n_nodes)
{
    const unsigned FULL = 0xffffffffu;
    const int lane = threadIdx.x & 31;
    const int warp = blockIdx.x * (blockDim.x >> 5) + (threadIdx.x >> 5);
    const int nw   = gridDim.x * (blockDim.x >> 5);

    for (int n = warp; n < n_nodes; n += nw) {
        float m = -3.4e38f;
        int idx0 = lane * 12;
#pragma unroll
        for (int i = 0; i < 12; i++) {
            int idx = idx0 + i;
            float v;
            if (idx < 128)       v = x2[(size_t)n * OC + idx];
            else if (idx < 256)  v = x4[(size_t)n * OC + idx - 128];
            else                 v = x6[(size_t)n * OC + idx - 256];
            m = fmaxf(m, v);
        }
        float mm = fmaxf(m, __shfl_xor_sync(FULL, m, 1));
        float part = ((lane & 1) == 0) ? mm * fw[lane >> 1] : 0.f;
#pragma unroll
        for (int off = 16; off >= 1; off >>= 1)
            part += __shfl_xor_sync(FULL, part, off);
        if (lane == 0) out[n] = part + fb[0];
    }
}

// ---------------------------------------------------------------------------
extern "C" void kernel_launch(void* const* d_in, const int* in_sizes, int n_in,
                              void* d_out, int out_size)
{
    const float* x   = (const float*)d_in[0];
    const void*  ei  = d_in[1];
    const float* w1a = (const float*)d_in[2];  const float* b1a = (const float*)d_in[3];
    const float* w1b = (const float*)d_in[4];  const float* b1b = (const float*)d_in[5];
    const float* w2a = (const float*)d_in[6];  const float* b2a = (const float*)d_in[7];
    const float* w2b = (const float*)d_in[8];  const float* b2b = (const float*)d_in[9];
    const float* w3a = (const float*)d_in[10]; const float* b3a = (const float*)d_in[11];
    const float* w3b = (const float*)d_in[12]; const float* b3b = (const float*)d_in[13];
    const float* fw  = (const float*)d_in[14]; const float* fb  = (const float*)d_in[15];
    float* out = (float*)d_out;

    const int       N = in_sizes[0] / 24;
    const long long E = in_sizes[1] / 2;

    float *A, *X2, *X4, *X6;
    __half *Bh;
    int *deg, *off, *cur, *ssrc, *sdst;
    uint4 *wbph;
    cudaGetSymbolAddress((void**)&A,    g_A);
    cudaGetSymbolAddress((void**)&Bh,   g_Bh);
    cudaGetSymbolAddress((void**)&X2,   g_x2);
    cudaGetSymbolAddress((void**)&X4,   g_x4);
    cudaGetSymbolAddress((void**)&X6,   g_x6);
    cudaGetSymbolAddress((void**)&deg,  g_deg);
    cudaGetSymbolAddress((void**)&off,  g_off);
    cudaGetSymbolAddress((void**)&cur,  g_cur);
    cudaGetSymbolAddress((void**)&ssrc, g_ssrc);
    cudaGetSymbolAddress((void**)&sdst, g_sdst);
    cudaGetSymbolAddress((void**)&wbph, g_wbph);

    cudaFuncSetAttribute(edge_mma_kernel,
                         cudaFuncAttributeMaxDynamicSharedMemorySize, SM_TOTAL);

    // ---- edge-index width + counting sort by dst ----
    detect_idx_kernel<<<1, 256>>>((const int*)ei);
    cudaMemsetAsync(deg, 0, (size_t)N * sizeof(int));
    cudaMemsetAsync(cur, 0, (size_t)N * sizeof(int));
    hist_kernel<<<512, 256>>>(ei, E, deg);
    scan_kernel<<<1, 1024>>>(deg, off, N);
    scatter_kernel<<<512, 256>>>(ei, E, off, cur, ssrc, sdst);

    // ---- weight prep (fp16 packed B fragments) ----
    prep_wh_kernel<<<8, 256>>>(w1b, wbph);
    prep_wh_kernel<<<8, 256>>>(w2b, wbph + 2048);
    prep_wh_kernel<<<8, 256>>>(w3b, wbph + 4096);

    const int NPB = 16;
    const int node_grid = (N + NPB - 1) / NPB;
    const int edge_grid = 296;   // 2 CTAs/SM

    // Layer 1 (C = 24)
    node_kernel<24, 16><<<node_grid, 128>>>(x, w1a, b1a, A, Bh, X2, N);
    edge_mma_kernel<<<edge_grid, 256, SM_TOTAL>>>((const float4*)A, (const uint4*)Bh,
        ssrc, sdst, wbph, b1b, X2, (int)E);
    // Layer 2 (C = 128)
    node_kernel<128, 16><<<node_grid, 128>>>(X2, w2a, b2a, A, Bh, X4, N);
    edge_mma_kernel<<<edge_grid, 256, SM_TOTAL>>>((const float4*)A, (const uint4*)Bh,
        ssrc, sdst, wbph + 2048, b2b, X4, (int)E);
    // Layer 3 (C = 128)
    node_kernel<128, 16><<<node_grid, 128>>>(X4, w3a, b3a, A, Bh, X6, N);
    edge_mma_kernel<<<edge_grid, 256, SM_TOTAL>>>((const float4*)A, (const uint4*)Bh,
        ssrc, sdst, wbph + 4096, b3b, X6, (int)E);

    // Pool + final linear
    final_kernel<<<(N + 7) / 8, 256>>>(X2, X4, X6, fw, fb, out, N);
}

// round 13
// speedup vs baseline: 2.3483x; 1.1033x over previous
#include <cuda_runtime.h>
#include <cuda_fp16.h>
#include <math.h>
#include <stdint.h>

#define NN   100000
#define OC   128
#define MAXE 1600000

// ---------------------------------------------------------------------------
// Device scratch
// ---------------------------------------------------------------------------
__device__ __align__(16) float  g_A [(size_t)NN * OC];
__device__ __align__(16) __half g_Bh[(size_t)NN * OC];
__device__ __align__(16) float  g_x2[(size_t)NN * OC];
__device__ __align__(16) float  g_x4[(size_t)NN * OC];
__device__ __align__(16) float  g_x6[(size_t)NN * OC];

__device__ int g_deg[NN];
__device__ int g_off[NN + 1];
__device__ int g_cur[NN];
__device__ int g_ssrc[MAXE];
__device__ int g_sdst[MAXE];
// fp16 edge-W fragments per layer: [wN(2)][kk(8)][p(4)][lane(32)] uint4
__device__ __align__(16) uint4 g_wbph[3][2048];
// tf32 node-W fragments (layers 2,3): [wN(4)][kk(16)][nt(8)][lane(32)] uint2
__device__ __align__(16) uint2 g_wap[2][16384];
__device__ int g_idx64;

// ---------------------------------------------------------------------------
// helpers
// ---------------------------------------------------------------------------
__device__ __forceinline__ uint32_t pack_h2(float lo, float hi) {
    __half2 h = __floats2half2_rn(lo, hi);
    return *(uint32_t*)&h;
}
__device__ __forceinline__ uint32_t f2tf32(float f) {
    uint32_t r;
    asm("cvt.rna.tf32.f32 %0, %1;" : "=r"(r) : "f"(f));
    return r;
}

__device__ __forceinline__ void mma_f16(float* d, const uint32_t* a,
                                        uint32_t b0, uint32_t b1) {
    asm volatile(
        "mma.sync.aligned.m16n8k16.row.col.f32.f16.f16.f32 "
        "{%0,%1,%2,%3}, {%4,%5,%6,%7}, {%8,%9}, {%0,%1,%2,%3};"
        : "+f"(d[0]), "+f"(d[1]), "+f"(d[2]), "+f"(d[3])
        : "r"(a[0]), "r"(a[1]), "r"(a[2]), "r"(a[3]), "r"(b0), "r"(b1));
}
__device__ __forceinline__ void mma_tf32(float* d, const uint32_t* a,
                                         uint32_t b0, uint32_t b1) {
    asm volatile(
        "mma.sync.aligned.m16n8k8.row.col.f32.tf32.tf32.f32 "
        "{%0,%1,%2,%3}, {%4,%5,%6,%7}, {%8,%9}, {%0,%1,%2,%3};"
        : "+f"(d[0]), "+f"(d[1]), "+f"(d[2]), "+f"(d[3])
        : "r"(a[0]), "r"(a[1]), "r"(a[2]), "r"(a[3]), "r"(b0), "r"(b1));
}

__device__ __forceinline__ uint32_t smem_u32(const void* p) {
    uint32_t a;
    asm("{ .reg .u64 t; cvta.to.shared.u64 t, %1; cvt.u32.u64 %0, t; }"
        : "=r"(a) : "l"(p));
    return a;
}

#define LDMATRIX_X4(r0, r1, r2, r3, addr) \
    asm volatile("ldmatrix.sync.aligned.m8n8.x4.shared.b16 {%0,%1,%2,%3}, [%4];" \
                 : "=r"(r0), "=r"(r1), "=r"(r2), "=r"(r3) : "r"(addr))

// ---------------------------------------------------------------------------
// Index-width detection (int32 vs int64 edge_index)
// ---------------------------------------------------------------------------
__global__ void detect_idx_kernel(const int* __restrict__ ei)
{
    __shared__ int any;
    if (threadIdx.x == 0) any = 0;
    __syncthreads();
    for (int i = threadIdx.x; i < 2048; i += blockDim.x)
        if (ei[2 * i + 1] != 0) any = 1;
    __syncthreads();
    if (threadIdx.x == 0) g_idx64 = (any == 0) ? 1 : 0;
}

// ---------------------------------------------------------------------------
// Counting sort by dst
// ---------------------------------------------------------------------------
__global__ void hist_kernel(const void* __restrict__ ei, long long E, int* __restrict__ deg)
{
    const int idx64 = g_idx64;
    long long i = (long long)blockIdx.x * blockDim.x + threadIdx.x;
    const long long stride = (long long)gridDim.x * blockDim.x;
    for (; i < E; i += stride) {
        int d = idx64 ? (int)((const long long*)ei)[E + i] : ((const int*)ei)[E + i];
        atomicAdd(&deg[d], 1);
    }
}

__global__ void scan_kernel(const int* __restrict__ deg, int* __restrict__ off, int n)
{
    __shared__ int sc[1024];
    __shared__ int carry;
    const int tid = threadIdx.x;
    if (tid == 0) carry = 0;
    __syncthreads();
    for (int base = 0; base < n; base += 1024) {
        int i = base + tid;
        int v = (i < n) ? deg[i] : 0;
        sc[tid] = v;
        __syncthreads();
        int run = v;
        for (int d = 1; d < 1024; d <<= 1) {
            int add = (tid >= d) ? sc[tid - d] : 0;
            __syncthreads();
            run += add;
            sc[tid] = run;
            __syncthreads();
        }
        int c = carry;
        if (i < n) off[i] = c + run - v;
        __syncthreads();
        if (tid == 0) carry = c + sc[1023];
        __syncthreads();
    }
    if (tid == 0) off[n] = carry;
}

__global__ void scatter_kernel(const void* __restrict__ ei, long long E,
                               const int* __restrict__ off, int* __restrict__ cur,
                               int* __restrict__ ssrc, int* __restrict__ sdst)
{
    const int idx64 = g_idx64;
    long long i = (long long)blockIdx.x * blockDim.x + threadIdx.x;
    const long long stride = (long long)gridDim.x * blockDim.x;
    for (; i < E; i += stride) {
        int s, d;
        if (idx64) { s = (int)((const long long*)ei)[i]; d = (int)((const long long*)ei)[E + i]; }
        else       { s = ((const int*)ei)[i];            d = ((const int*)ei)[E + i]; }
        int p = off[d] + atomicAdd(&cur[d], 1);
        ssrc[p] = s;
        sdst[p] = d;
    }
}

// ---------------------------------------------------------------------------
// Pack wb [K=128][N=128] -> fp16 B fragments for m16n8k16 (edge GEMM)
// ---------------------------------------------------------------------------
__global__ void prep_wh_kernel(const float* __restrict__ wb, uint4* __restrict__ outp)
{
    int idx = blockIdx.x * blockDim.x + threadIdx.x;
    if (idx >= 2048) return;
    int lane = idx & 31;
    int p    = (idx >> 5) & 3;
    int kk   = (idx >> 7) & 7;
    int wN   = idx >> 10;
    int g  = lane >> 2, th = lane & 3;
    int n0 = wN * 64 + p * 16 + g;
    int n1 = n0 + 8;
    int k0 = kk * 16 + 2 * th;
    uint4 v;
    v.x = pack_h2(wb[k0 * 128 + n0],       wb[(k0 + 1) * 128 + n0]);
    v.y = pack_h2(wb[(k0 + 8) * 128 + n0], wb[(k0 + 9) * 128 + n0]);
    v.z = pack_h2(wb[k0 * 128 + n1],       wb[(k0 + 1) * 128 + n1]);
    v.w = pack_h2(wb[(k0 + 8) * 128 + n1], wb[(k0 + 9) * 128 + n1]);
    outp[idx] = v;
}

// ---------------------------------------------------------------------------
// Pack wa [2*128][128] -> tf32 fragments for combined node GEMM (m16n8k8).
// Wc[k][n]       = wa[k][n] - wa[128+k][n]   (n < 128, "A" half)
// Wc[k][128 + n] = wa[128+k][n]              ("B" half)
// Layout: idx = wN*4096 + kk*256 + nt*32 + lane  (wN at bit 12!)
//   uint2 {b0 = Wc[k0][n], b1 = Wc[k0+4][n]}, k0 = kk*8 + th, n = wN*64 + nt*8 + g
// ---------------------------------------------------------------------------
__global__ void prep_wa_kernel(const float* __restrict__ wa, uint2* __restrict__ outp)
{
    int idx = blockIdx.x * blockDim.x + threadIdx.x;
    if (idx >= 16384) return;
    int lane = idx & 31;
    int nt   = (idx >> 5) & 7;
    int kk   = (idx >> 8) & 15;
    int wN   = idx >> 12;        // FIXED: was >> 11, aliased kk's top bit
    int g = lane >> 2, th = lane & 3;
    int n  = wN * 64 + nt * 8 + g;
    int k0 = kk * 8 + th;
    float w0, w1;
    if (n < 128) {
        w0 = wa[k0 * 128 + n]       - wa[(128 + k0) * 128 + n];
        w1 = wa[(k0 + 4) * 128 + n] - wa[(132 + k0) * 128 + n];
    } else {
        int nn = n - 128;
        w0 = wa[(128 + k0) * 128 + nn];
        w1 = wa[(132 + k0) * 128 + nn];
    }
    outp[idx] = make_uint2(f2tf32(w0), f2tf32(w1));
}

// ---------------------------------------------------------------------------
// Scalar node transform (layer 1 only, C = 24)
// ---------------------------------------------------------------------------
template<int C, int NPB>
__global__ __launch_bounds__(128)
void node_kernel(const float* __restrict__ x,
                 const float* __restrict__ wa,
                 const float* __restrict__ ba,
                 float* __restrict__ A,
                 __half* __restrict__ Bh,
                 float* __restrict__ outz,
                 int n_nodes)
{
    __shared__ float xs[NPB * C];
    const int n0  = blockIdx.x * NPB;
    const int tid = threadIdx.x;

    for (int i = tid; i < NPB * C; i += 128) {
        int nn = i / C, c = i % C;
        int n = n0 + nn;
        xs[i] = (n < n_nodes) ? x[(size_t)n * C + c] : 0.f;
    }
    __syncthreads();

    float a[NPB], b[NPB];
#pragma unroll
    for (int t = 0; t < NPB; t++) { a[t] = 0.f; b[t] = 0.f; }

    const int o = tid;
#pragma unroll 4
    for (int c = 0; c < C; c++) {
        float wtop = wa[(size_t)c       * OC + o];
        float wbot = wa[(size_t)(C + c) * OC + o];
        float wd   = wtop - wbot;
#pragma unroll
        for (int t = 0; t < NPB; t++) {
            float xv = xs[t * C + c];
            a[t] += xv * wd;
            b[t] += xv * wbot;
        }
    }
    float bao = ba[o];
#pragma unroll
    for (int t = 0; t < NPB; t++) {
        int n = n0 + t;
        if (n < n_nodes) {
            size_t idx = (size_t)n * OC + o;
            A[idx]    = a[t] + bao;
            Bh[idx]   = __float2half(b[t]);
            outz[idx] = 0.f;
        }
    }
}

// ---------------------------------------------------------------------------
// Tensor node transform (C = 128 layers): [64 nodes] x [256 outs] per CTA.
// 8 warps = 2(M) x 4(N); warp tile 32 nodes x 64 outs, tf32 m16n8k8.
// wN 0,1 -> A = acc + ba (fp32) and outz = 0 ; wN 2,3 -> Bh = fp16(acc).
// ---------------------------------------------------------------------------
#define NXS 132

__global__ __launch_bounds__(256, 2)
void node_mma_kernel(const float* __restrict__ x,
                     const uint2* __restrict__ wap,
                     const float* __restrict__ ba,
                     float* __restrict__ A,
                     __half* __restrict__ Bh,
                     float* __restrict__ outz,
                     int n_nodes)
{
    __shared__ uint32_t xs[64 * NXS];
    const int tid  = threadIdx.x;
    const int wid  = tid >> 5;
    const int lane = tid & 31;
    const int n0   = blockIdx.x * 64;

    // stage x rows (tf32) : 64 rows x 32 float4
    for (int i = tid; i < 64 * 32; i += 256) {
        int r = i >> 5, q = i & 31;
        uint4 v;
        if (n0 + r < n_nodes) {
            float4 f = *(const float4*)(x + (size_t)(n0 + r) * 128 + q * 4);
            v.x = f2tf32(f.x); v.y = f2tf32(f.y);
            v.z = f2tf32(f.z); v.w = f2tf32(f.w);
        } else {
            v = make_uint4(0u, 0u, 0u, 0u);
        }
        *(uint4*)(xs + r * NXS + q * 4) = v;
    }
    __syncthreads();

    const int wM = wid & 1;      // node half  [wM*32, +32)
    const int wN = wid >> 1;     // out quarter [wN*64, +64)
    const int g = lane >> 2, th = lane & 3;

    float acc[2][8][4];
#pragma unroll
    for (int mt = 0; mt < 2; mt++)
#pragma unroll
        for (int nt = 0; nt < 8; nt++)
#pragma unroll
            for (int r = 0; r < 4; r++) acc[mt][nt][r] = 0.f;

    const uint2* wrow = wap + (size_t)wN * 4096 + lane;
#pragma unroll 4
    for (int kk = 0; kk < 16; kk++) {
        uint32_t a[2][4];
#pragma unroll
        for (int mt = 0; mt < 2; mt++) {
            const uint32_t* base = xs + (wM * 32 + mt * 16 + g) * NXS + kk * 8 + th;
            a[mt][0] = base[0];
            a[mt][1] = base[8 * NXS];
            a[mt][2] = base[4];
            a[mt][3] = base[8 * NXS + 4];
        }
#pragma unroll
        for (int nt = 0; nt < 8; nt++) {
            uint2 bp = wrow[(kk * 8 + nt) * 32];
#pragma unroll
            for (int mt = 0; mt < 2; mt++)
                mma_tf32(acc[mt][nt], a[mt], bp.x, bp.y);
        }
    }

    // epilogue
#pragma unroll
    for (int mt = 0; mt < 2; mt++) {
        const int row = wM * 32 + mt * 16 + g;
#pragma unroll
        for (int nt = 0; nt < 8; nt++) {
            const int col = wN * 64 + nt * 8 + 2 * th;
            if (wN < 2) {
                float b0 = ba[col], b1 = ba[col + 1];
                int n = n0 + row;
                if (n < n_nodes) {
                    size_t i0 = (size_t)n * OC + col;
                    *(float2*)(A + i0) = make_float2(acc[mt][nt][0] + b0,
                                                     acc[mt][nt][1] + b1);
                    *(float2*)(outz + i0) = make_float2(0.f, 0.f);
                }
                n = n0 + row + 8;
                if (n < n_nodes) {
                    size_t i1 = (size_t)n * OC + col;
                    *(float2*)(A + i1) = make_float2(acc[mt][nt][2] + b0,
                                                     acc[mt][nt][3] + b1);
                    *(float2*)(outz + i1) = make_float2(0.f, 0.f);
                }
            } else {
                const int oc = col - 128;
                int n = n0 + row;
                if (n < n_nodes) {
                    __half2 h = __floats2half2_rn(acc[mt][nt][0], acc[mt][nt][1]);
                    *(__half2*)(Bh + (size_t)n * OC + oc) = h;
                }
                n = n0 + row + 8;
                if (n < n_nodes) {
                    __half2 h = __floats2half2_rn(acc[mt][nt][2], acc[mt][nt][3]);
                    *(__half2*)(Bh + (size_t)n * OC + oc) = h;
                }
            }
        }
    }
}

// ---------------------------------------------------------------------------
// Edge kernel (mma.sync fp16 m16n8k16, sorted edges, 2 CTAs/SM).
// ---------------------------------------------------------------------------
#define HP  132
#define HHW 68

#define SM_H     0
#define SM_SDST  67584
#define SM_SSRC  (SM_SDST + 512)
#define SM_SEGS  (SM_SSRC + 512)
#define SM_SEGN  (SM_SEGS + 544)
#define SM_BB    (SM_SEGN + 512)
#define SM_WC    (SM_BB + 512)
#define SM_NSEG  (SM_WC + 32)
#define SM_TOTAL (SM_NSEG + 16)

__global__ __launch_bounds__(256, 2)
void edge_mma_kernel(const float4* __restrict__ nodeA,
                     const uint4*  __restrict__ nodeBh,
                     const int* __restrict__ ssrc_g,
                     const int* __restrict__ sdst_g,
                     const uint4* __restrict__ wbph,
                     const float* __restrict__ bb,
                     float* __restrict__ out,
                     int E)
{
    extern __shared__ __align__(16) char smem[];
    const int tid  = threadIdx.x;
    const int wid  = tid >> 5;
    const int lane = tid & 31;
    const unsigned FULL = 0xffffffffu;

    uint32_t* Hw   = (uint32_t*)(smem + SM_H);
    float*    msg  = (float*)(smem + SM_H);
    int*      sdst = (int*)(smem + SM_SDST);
    int*      ssrc = (int*)(smem + SM_SSRC);
    int*      segs = (int*)(smem + SM_SEGS);
    int*      segn = (int*)(smem + SM_SEGN);
    float*    bbs  = (float*)(smem + SM_BB);
    int*      swc  = (int*)(smem + SM_WC);
    int*      snseg= (int*)(smem + SM_NSEG);

    if (tid < 128) bbs[tid] = bb[tid];

    const int ntiles = (E + 127) >> 7;
    const int wM = wid & 3;
    const int wN = wid >> 2;

    const int lm_m   = lane >> 3;
    const int lm_row = (lane & 7) + ((lm_m & 1) << 3);
    const int lm_cw  = (lm_m >> 1) * 4;
    uint32_t lm_addr[2];
#pragma unroll
    for (int mt = 0; mt < 2; mt++)
        lm_addr[mt] = smem_u32(Hw + (wM * 32 + mt * 16 + lm_row) * HHW + lm_cw);

    for (int t = blockIdx.x; t < ntiles; t += gridDim.x) {
        const int e0  = t << 7;
        const int cnt = min(128, E - e0);

        if (tid < 128) {
            sdst[tid] = (tid < cnt) ? sdst_g[e0 + tid] : -1;
            ssrc[tid] = (tid < cnt) ? ssrc_g[e0 + tid] : 0;
        }
        __syncthreads();

        int head = 0; unsigned bm = 0;
        if (tid < 128) {
            head = (tid < cnt) && (tid == 0 || sdst[tid] != sdst[tid - 1]);
            bm = __ballot_sync(FULL, head);
            if (lane == 0) swc[wid] = __popc(bm);
        }
        __syncthreads();
        if (tid == 0) {
            int s = 0;
            for (int w = 0; w < 4; w++) { swc[4 + w] = s; s += swc[w]; }
            snseg[0] = s;
            segs[s]  = cnt;
        }
        __syncthreads();
        if (head) {
            int sid = swc[4 + wid] + __popc(bm & ((1u << lane) - 1u));
            segs[sid] = tid;
            segn[sid] = sdst[tid];
        }

        // gather: H[e][k] = fp16(relu(A_f32[dst] + Bh[src]))
        {
            const int e    = tid >> 1;
            const int half = tid & 1;
            uint4* hrow = (uint4*)Hw + e * (HHW / 4) + half * 8;
            if (e < cnt) {
                const float4* arow = nodeA  + (size_t)sdst[e] * 32 + half * 16;
                const uint4*  brow = nodeBh + (size_t)ssrc[e] * 16 + half * 8;
#pragma unroll
                for (int m = 0; m < 8; m++) {
                    float4 a0 = arow[2 * m];
                    float4 a1 = arow[2 * m + 1];
                    uint4  bv = brow[m];
                    float2 f0 = __half22float2(*(__half2*)&bv.x);
                    float2 f1 = __half22float2(*(__half2*)&bv.y);
                    float2 f2 = __half22float2(*(__half2*)&bv.z);
                    float2 f3 = __half22float2(*(__half2*)&bv.w);
                    uint4 w;
                    w.x = pack_h2(fmaxf(a0.x + f0.x, 0.f), fmaxf(a0.y + f0.y, 0.f));
                    w.y = pack_h2(fmaxf(a0.z + f1.x, 0.f), fmaxf(a0.w + f1.y, 0.f));
                    w.z = pack_h2(fmaxf(a1.x + f2.x, 0.f), fmaxf(a1.y + f2.y, 0.f));
                    w.w = pack_h2(fmaxf(a1.z + f3.x, 0.f), fmaxf(a1.w + f3.y, 0.f));
                    hrow[m] = w;
                }
            } else {
#pragma unroll
                for (int m = 0; m < 8; m++)
                    hrow[m] = make_uint4(0u, 0u, 0u, 0u);
            }
        }
        __syncthreads();

        // MMA: warp tile 32 edges x 64 outs
        float acc[2][8][4];
#pragma unroll
        for (int mt = 0; mt < 2; mt++)
#pragma unroll
            for (int nt = 0; nt < 8; nt++)
#pragma unroll
                for (int r = 0; r < 4; r++) acc[mt][nt][r] = 0.f;

        const int g = lane >> 2, th = lane & 3;
        const uint4* wrow = wbph + (size_t)wN * 1024 + lane;
#pragma unroll
        for (int kk = 0; kk < 8; kk++) {
            uint32_t a[2][4];
#pragma unroll
            for (int mt = 0; mt < 2; mt++)
                LDMATRIX_X4(a[mt][0], a[mt][1], a[mt][2], a[mt][3],
                            lm_addr[mt] + kk * 32);
#pragma unroll
            for (int p = 0; p < 4; p++) {
                uint4 bp = wrow[kk * 128 + p * 32];
#pragma unroll
                for (int mt = 0; mt < 2; mt++) {
                    mma_f16(acc[mt][2 * p],     a[mt], bp.x, bp.y);
                    mma_f16(acc[mt][2 * p + 1], a[mt], bp.z, bp.w);
                }
            }
        }
        __syncthreads();

        // store D -> msg[e][c]
#pragma unroll
        for (int mt = 0; mt < 2; mt++) {
            const int row = wM * 32 + mt * 16 + g;
#pragma unroll
            for (int nt = 0; nt < 8; nt++) {
                const int col = wN * 64 + nt * 8 + 2 * th;
                *(float2*)(msg + row * HP + col) =
                    make_float2(acc[mt][nt][0], acc[mt][nt][1]);
                *(float2*)(msg + (row + 8) * HP + col) =
                    make_float2(acc[mt][nt][2], acc[mt][nt][3]);
            }
        }
        __syncthreads();

        // segmented max + writeback
        {
            const int nseg = snseg[0];
            for (int i = tid; i < nseg * 128; i += 256) {
                const int c = i & 127;
                const int s = i >> 7;
                const int st = segs[s], en = segs[s + 1];
                float m = -3.4e38f;
                for (int e = st; e < en; e++)
                    m = fmaxf(m, msg[e * HP + c]);
                m += bbs[c];
                float* o = out + (size_t)segn[s] * OC + c;
                if (st == 0 || en == cnt) {
                    atomicMax((int*)o, __float_as_int(m));
                } else {
                    *o = fmaxf(m, 0.f);
                }
            }
        }
        __syncthreads();
    }
}

// ---------------------------------------------------------------------------
// Final: concat(x2,x4,x6) [384] -> maxpool(24) -> 16 -> @ fw + fb
// ---------------------------------------------------------------------------
__global__ __launch_bounds__(256)
void final_kernel(const float* __restrict__ x2,
                  const float* __restrict__ x4,
                  const float* __restrict__ x6,
                  const float* __restrict__ fw,
                  const float* __restrict__ fb,
                  float* __restrict__ out,
                  int n_nodes)
{
    const unsigned FULL = 0xffffffffu;
    const int lane = threadIdx.x & 31;
    const int warp = blockIdx.x * (blockDim.x >> 5) + (threadIdx.x >> 5);
    const int nw   = gridDim.x * (blockDim.x >> 5);

    for (int n = warp; n < n_nodes; n += nw) {
        float m = -3.4e38f;
        int idx0 = lane * 12;
#pragma unroll
        for (int i = 0; i < 12; i++) {
            int idx = idx0 + i;
            float v;
            if (idx < 128)       v = x2[(size_t)n * OC + idx];
            else if (idx < 256)  v = x4[(size_t)n * OC + idx - 128];
            else                 v = x6[(size_t)n * OC + idx - 256];
            m = fmaxf(m, v);
        }
        float mm = fmaxf(m, __shfl_xor_sync(FULL, m, 1));
        float part = ((lane & 1) == 0) ? mm * fw[lane >> 1] : 0.f;
#pragma unroll
        for (int off = 16; off >= 1; off >>= 1)
            part += __shfl_xor_sync(FULL, part, off);
        if (lane == 0) out[n] = part + fb[0];
    }
}

// ---------------------------------------------------------------------------
extern "C" void kernel_launch(void* const* d_in, const int* in_sizes, int n_in,
                              void* d_out, int out_size)
{
    const float* x   = (const float*)d_in[0];
    const void*  ei  = d_in[1];
    const float* w1a = (const float*)d_in[2];  const float* b1a = (const float*)d_in[3];
    const float* w1b = (const float*)d_in[4];  const float* b1b = (const float*)d_in[5];
    const float* w2a = (const float*)d_in[6];  const float* b2a = (const float*)d_in[7];
    const float* w2b = (const float*)d_in[8];  const float* b2b = (const float*)d_in[9];
    const float* w3a = (const float*)d_in[10]; const float* b3a = (const float*)d_in[11];
    const float* w3b = (const float*)d_in[12]; const float* b3b = (const float*)d_in[13];
    const float* fw  = (const float*)d_in[14]; const float* fb  = (const float*)d_in[15];
    float* out = (float*)d_out;

    const int       N = in_sizes[0] / 24;
    const long long E = in_sizes[1] / 2;

    float *A, *X2, *X4, *X6;
    __half *Bh;
    int *deg, *off, *cur, *ssrc, *sdst;
    uint4 *wbph;
    uint2 *wap;
    cudaGetSymbolAddress((void**)&A,    g_A);
    cudaGetSymbolAddress((void**)&Bh,   g_Bh);
    cudaGetSymbolAddress((void**)&X2,   g_x2);
    cudaGetSymbolAddress((void**)&X4,   g_x4);
    cudaGetSymbolAddress((void**)&X6,   g_x6);
    cudaGetSymbolAddress((void**)&deg,  g_deg);
    cudaGetSymbolAddress((void**)&off,  g_off);
    cudaGetSymbolAddress((void**)&cur,  g_cur);
    cudaGetSymbolAddress((void**)&ssrc, g_ssrc);
    cudaGetSymbolAddress((void**)&sdst, g_sdst);
    cudaGetSymbolAddress((void**)&wbph, g_wbph);
    cudaGetSymbolAddress((void**)&wap,  g_wap);

    cudaFuncSetAttribute(edge_mma_kernel,
                         cudaFuncAttributeMaxDynamicSharedMemorySize, SM_TOTAL);

    // ---- edge-index width + counting sort by dst ----
    detect_idx_kernel<<<1, 256>>>((const int*)ei);
    cudaMemsetAsync(deg, 0, (size_t)N * sizeof(int));
    cudaMemsetAsync(cur, 0, (size_t)N * sizeof(int));
    hist_kernel<<<512, 256>>>(ei, E, deg);
    scan_kernel<<<1, 1024>>>(deg, off, N);
    scatter_kernel<<<512, 256>>>(ei, E, off, cur, ssrc, sdst);

    // ---- weight prep ----
    prep_wh_kernel<<<8, 256>>>(w1b, wbph);
    prep_wh_kernel<<<8, 256>>>(w2b, wbph + 2048);
    prep_wh_kernel<<<8, 256>>>(w3b, wbph + 4096);
    prep_wa_kernel<<<64, 256>>>(w2a, wap);
    prep_wa_kernel<<<64, 256>>>(w3a, wap + 16384);

    const int node1_grid = (N + 15) / 16;
    const int nodem_grid = (N + 63) / 64;
    const int edge_grid  = 296;   // 2 CTAs/SM

    // Layer 1 (C = 24, scalar)
    node_kernel<24, 16><<<node1_grid, 128>>>(x, w1a, b1a, A, Bh, X2, N);
    edge_mma_kernel<<<edge_grid, 256, SM_TOTAL>>>((const float4*)A, (const uint4*)Bh,
        ssrc, sdst, wbph, b1b, X2, (int)E);
    // Layer 2 (C = 128, tf32 mma)
    node_mma_kernel<<<nodem_grid, 256>>>(X2, wap, b2a, A, Bh, X4, N);
    edge_mma_kernel<<<edge_grid, 256, SM_TOTAL>>>((const float4*)A, (const uint4*)Bh,
        ssrc, sdst, wbph + 2048, b2b, X4, (int)E);
    // Layer 3 (C = 128, tf32 mma)
    node_mma_kernel<<<nodem_grid, 256>>>(X4, wap + 16384, b3a, A, Bh, X6, N);
    edge_mma_kernel<<<edge_grid, 256, SM_TOTAL>>>((const float4*)A, (const uint4*)Bh,
        ssrc, sdst, wbph + 4096, b3b, X6, (int)E);

    // Pool + final linear
    final_kernel<<<(N + 7) / 8, 256>>>(X2, X4, X6, fw, fb, out, N);
}

// round 14
// speedup vs baseline: 2.4259x; 1.0330x over previous
#include <cuda_runtime.h>
#include <cuda_fp16.h>
#include <math.h>
#include <stdint.h>

#define NN   100000
#define OC   128
#define MAXE 1600000

// ---------------------------------------------------------------------------
// Device scratch
// ---------------------------------------------------------------------------
__device__ __align__(16) float  g_A [(size_t)NN * OC];
__device__ __align__(16) __half g_Bh[(size_t)NN * OC];
__device__ __align__(16) float  g_x2[(size_t)NN * OC];
__device__ __align__(16) float  g_x4[(size_t)NN * OC];
__device__ __align__(16) float  g_x6[(size_t)NN * OC];

__device__ int g_deg[NN];
__device__ int g_off[NN + 1];
__device__ int g_cur[NN];
__device__ int g_ssrc[MAXE];
__device__ int g_sdst[MAXE];
// fp16 edge-W fragments per layer: [wN(2)][kk(8)][p(4)][lane(32)] uint4
__device__ __align__(16) uint4 g_wbph[3][2048];
// tf32 node-W fragments (layers 2,3): [wN(4)][kk(16)][nt(8)][lane(32)] uint2
__device__ __align__(16) uint2 g_wap[2][16384];
__device__ int g_idx64;

// ---------------------------------------------------------------------------
// helpers
// ---------------------------------------------------------------------------
__device__ __forceinline__ uint32_t pack_h2(float lo, float hi) {
    __half2 h = __floats2half2_rn(lo, hi);
    return *(uint32_t*)&h;
}
__device__ __forceinline__ uint32_t f2tf32(float f) {
    uint32_t r;
    asm("cvt.rna.tf32.f32 %0, %1;" : "=r"(r) : "f"(f));
    return r;
}

__device__ __forceinline__ void mma_f16(float* d, const uint32_t* a,
                                        uint32_t b0, uint32_t b1) {
    asm volatile(
        "mma.sync.aligned.m16n8k16.row.col.f32.f16.f16.f32 "
        "{%0,%1,%2,%3}, {%4,%5,%6,%7}, {%8,%9}, {%0,%1,%2,%3};"
        : "+f"(d[0]), "+f"(d[1]), "+f"(d[2]), "+f"(d[3])
        : "r"(a[0]), "r"(a[1]), "r"(a[2]), "r"(a[3]), "r"(b0), "r"(b1));
}
__device__ __forceinline__ void mma_tf32(float* d, const uint32_t* a,
                                         uint32_t b0, uint32_t b1) {
    asm volatile(
        "mma.sync.aligned.m16n8k8.row.col.f32.tf32.tf32.f32 "
        "{%0,%1,%2,%3}, {%4,%5,%6,%7}, {%8,%9}, {%0,%1,%2,%3};"
        : "+f"(d[0]), "+f"(d[1]), "+f"(d[2]), "+f"(d[3])
        : "r"(a[0]), "r"(a[1]), "r"(a[2]), "r"(a[3]), "r"(b0), "r"(b1));
}

__device__ __forceinline__ uint32_t smem_u32(const void* p) {
    uint32_t a;
    asm("{ .reg .u64 t; cvta.to.shared.u64 t, %1; cvt.u32.u64 %0, t; }"
        : "=r"(a) : "l"(p));
    return a;
}

#define LDMATRIX_X4(r0, r1, r2, r3, addr) \
    asm volatile("ldmatrix.sync.aligned.m8n8.x4.shared.b16 {%0,%1,%2,%3}, [%4];" \
                 : "=r"(r0), "=r"(r1), "=r"(r2), "=r"(r3) : "r"(addr))

// ---------------------------------------------------------------------------
// Index-width detection (int32 vs int64 edge_index)
// ---------------------------------------------------------------------------
__global__ void detect_idx_kernel(const int* __restrict__ ei)
{
    __shared__ int any;
    if (threadIdx.x == 0) any = 0;
    __syncthreads();
    for (int i = threadIdx.x; i < 2048; i += blockDim.x)
        if (ei[2 * i + 1] != 0) any = 1;
    __syncthreads();
    if (threadIdx.x == 0) g_idx64 = (any == 0) ? 1 : 0;
}

// ---------------------------------------------------------------------------
// Counting sort by dst
// ---------------------------------------------------------------------------
__global__ void hist_kernel(const void* __restrict__ ei, long long E, int* __restrict__ deg)
{
    const int idx64 = g_idx64;
    long long i = (long long)blockIdx.x * blockDim.x + threadIdx.x;
    const long long stride = (long long)gridDim.x * blockDim.x;
    for (; i < E; i += stride) {
        int d = idx64 ? (int)((const long long*)ei)[E + i] : ((const int*)ei)[E + i];
        atomicAdd(&deg[d], 1);
    }
}

// Warp-shuffle scan: 4 barriers per 1024-chunk instead of 20.
__global__ void scan_kernel(const int* __restrict__ deg, int* __restrict__ off, int n)
{
    const unsigned FULL = 0xffffffffu;
    __shared__ int wsum[32];
    __shared__ int carry_s;
    const int tid  = threadIdx.x;
    const int lane = tid & 31;
    const int wid  = tid >> 5;
    if (tid == 0) carry_s = 0;
    __syncthreads();
    for (int base = 0; base < n; base += 1024) {
        int i = base + tid;
        int v = (i < n) ? deg[i] : 0;
        int s = v;
#pragma unroll
        for (int d = 1; d < 32; d <<= 1) {
            int t = __shfl_up_sync(FULL, s, d);
            if (lane >= d) s += t;
        }
        if (lane == 31) wsum[wid] = s;
        __syncthreads();
        if (wid == 0) {
            int w = wsum[lane];
#pragma unroll
            for (int d = 1; d < 32; d <<= 1) {
                int t = __shfl_up_sync(FULL, w, d);
                if (lane >= d) w += t;
            }
            wsum[lane] = w;
        }
        __syncthreads();
        int carry = carry_s;
        if (i < n) off[i] = carry + (wid ? wsum[wid - 1] : 0) + s - v;
        __syncthreads();
        if (tid == 0) carry_s = carry + wsum[31];
        __syncthreads();
    }
    if (threadIdx.x == 0) off[n] = carry_s;
}

__global__ void scatter_kernel(const void* __restrict__ ei, long long E,
                               const int* __restrict__ off, int* __restrict__ cur,
                               int* __restrict__ ssrc, int* __restrict__ sdst)
{
    const int idx64 = g_idx64;
    long long i = (long long)blockIdx.x * blockDim.x + threadIdx.x;
    const long long stride = (long long)gridDim.x * blockDim.x;
    for (; i < E; i += stride) {
        int s, d;
        if (idx64) { s = (int)((const long long*)ei)[i]; d = (int)((const long long*)ei)[E + i]; }
        else       { s = ((const int*)ei)[i];            d = ((const int*)ei)[E + i]; }
        int p = off[d] + atomicAdd(&cur[d], 1);
        ssrc[p] = s;
        sdst[p] = d;
    }
}

// ---------------------------------------------------------------------------
// Pack wb [K=128][N=128] -> fp16 B fragments for m16n8k16 (edge GEMM)
// ---------------------------------------------------------------------------
__global__ void prep_wh_kernel(const float* __restrict__ wb, uint4* __restrict__ outp)
{
    int idx = blockIdx.x * blockDim.x + threadIdx.x;
    if (idx >= 2048) return;
    int lane = idx & 31;
    int p    = (idx >> 5) & 3;
    int kk   = (idx >> 7) & 7;
    int wN   = idx >> 10;
    int g  = lane >> 2, th = lane & 3;
    int n0 = wN * 64 + p * 16 + g;
    int n1 = n0 + 8;
    int k0 = kk * 16 + 2 * th;
    uint4 v;
    v.x = pack_h2(wb[k0 * 128 + n0],       wb[(k0 + 1) * 128 + n0]);
    v.y = pack_h2(wb[(k0 + 8) * 128 + n0], wb[(k0 + 9) * 128 + n0]);
    v.z = pack_h2(wb[k0 * 128 + n1],       wb[(k0 + 1) * 128 + n1]);
    v.w = pack_h2(wb[(k0 + 8) * 128 + n1], wb[(k0 + 9) * 128 + n1]);
    outp[idx] = v;
}

// ---------------------------------------------------------------------------
// Pack wa [2*128][128] -> tf32 fragments for combined node GEMM (m16n8k8).
// idx = wN*4096 + kk*256 + nt*32 + lane (wN at bit 12)
// ---------------------------------------------------------------------------
__global__ void prep_wa_kernel(const float* __restrict__ wa, uint2* __restrict__ outp)
{
    int idx = blockIdx.x * blockDim.x + threadIdx.x;
    if (idx >= 16384) return;
    int lane = idx & 31;
    int nt   = (idx >> 5) & 7;
    int kk   = (idx >> 8) & 15;
    int wN   = idx >> 12;
    int g = lane >> 2, th = lane & 3;
    int n  = wN * 64 + nt * 8 + g;
    int k0 = kk * 8 + th;
    float w0, w1;
    if (n < 128) {
        w0 = wa[k0 * 128 + n]       - wa[(128 + k0) * 128 + n];
        w1 = wa[(k0 + 4) * 128 + n] - wa[(132 + k0) * 128 + n];
    } else {
        int nn = n - 128;
        w0 = wa[(128 + k0) * 128 + nn];
        w1 = wa[(132 + k0) * 128 + nn];
    }
    outp[idx] = make_uint2(f2tf32(w0), f2tf32(w1));
}

// ---------------------------------------------------------------------------
// Scalar node transform (layer 1 only, C = 24)
// ---------------------------------------------------------------------------
template<int C, int NPB>
__global__ __launch_bounds__(128)
void node_kernel(const float* __restrict__ x,
                 const float* __restrict__ wa,
                 const float* __restrict__ ba,
                 float* __restrict__ A,
                 __half* __restrict__ Bh,
                 float* __restrict__ outz,
                 int n_nodes)
{
    __shared__ float xs[NPB * C];
    const int n0  = blockIdx.x * NPB;
    const int tid = threadIdx.x;

    for (int i = tid; i < NPB * C; i += 128) {
        int nn = i / C, c = i % C;
        int n = n0 + nn;
        xs[i] = (n < n_nodes) ? x[(size_t)n * C + c] : 0.f;
    }
    __syncthreads();

    float a[NPB], b[NPB];
#pragma unroll
    for (int t = 0; t < NPB; t++) { a[t] = 0.f; b[t] = 0.f; }

    const int o = tid;
#pragma unroll 4
    for (int c = 0; c < C; c++) {
        float wtop = wa[(size_t)c       * OC + o];
        float wbot = wa[(size_t)(C + c) * OC + o];
        float wd   = wtop - wbot;
#pragma unroll
        for (int t = 0; t < NPB; t++) {
            float xv = xs[t * C + c];
            a[t] += xv * wd;
            b[t] += xv * wbot;
        }
    }
    float bao = ba[o];
#pragma unroll
    for (int t = 0; t < NPB; t++) {
        int n = n0 + t;
        if (n < n_nodes) {
            size_t idx = (size_t)n * OC + o;
            A[idx]    = a[t] + bao;
            Bh[idx]   = __float2half(b[t]);
            outz[idx] = 0.f;
        }
    }
}

// ---------------------------------------------------------------------------
// Tensor node transform (C = 128 layers), tf32 m16n8k8, 64 nodes x 256 outs.
// ---------------------------------------------------------------------------
#define NXS 132

__global__ __launch_bounds__(256, 2)
void node_mma_kernel(const float* __restrict__ x,
                     const uint2* __restrict__ wap,
                     const float* __restrict__ ba,
                     float* __restrict__ A,
                     __half* __restrict__ Bh,
                     float* __restrict__ outz,
                     int n_nodes)
{
    __shared__ uint32_t xs[64 * NXS];
    const int tid  = threadIdx.x;
    const int wid  = tid >> 5;
    const int lane = tid & 31;
    const int n0   = blockIdx.x * 64;

    for (int i = tid; i < 64 * 32; i += 256) {
        int r = i >> 5, q = i & 31;
        uint4 v;
        if (n0 + r < n_nodes) {
            float4 f = *(const float4*)(x + (size_t)(n0 + r) * 128 + q * 4);
            v.x = f2tf32(f.x); v.y = f2tf32(f.y);
            v.z = f2tf32(f.z); v.w = f2tf32(f.w);
        } else {
            v = make_uint4(0u, 0u, 0u, 0u);
        }
        *(uint4*)(xs + r * NXS + q * 4) = v;
    }
    __syncthreads();

    const int wM = wid & 1;
    const int wN = wid >> 1;
    const int g = lane >> 2, th = lane & 3;

    float acc[2][8][4];
#pragma unroll
    for (int mt = 0; mt < 2; mt++)
#pragma unroll
        for (int nt = 0; nt < 8; nt++)
#pragma unroll
            for (int r = 0; r < 4; r++) acc[mt][nt][r] = 0.f;

    const uint2* wrow = wap + (size_t)wN * 4096 + lane;
#pragma unroll 4
    for (int kk = 0; kk < 16; kk++) {
        uint32_t a[2][4];
#pragma unroll
        for (int mt = 0; mt < 2; mt++) {
            const uint32_t* base = xs + (wM * 32 + mt * 16 + g) * NXS + kk * 8 + th;
            a[mt][0] = base[0];
            a[mt][1] = base[8 * NXS];
            a[mt][2] = base[4];
            a[mt][3] = base[8 * NXS + 4];
        }
#pragma unroll
        for (int nt = 0; nt < 8; nt++) {
            uint2 bp = wrow[(kk * 8 + nt) * 32];
#pragma unroll
            for (int mt = 0; mt < 2; mt++)
                mma_tf32(acc[mt][nt], a[mt], bp.x, bp.y);
        }
    }

#pragma unroll
    for (int mt = 0; mt < 2; mt++) {
        const int row = wM * 32 + mt * 16 + g;
#pragma unroll
        for (int nt = 0; nt < 8; nt++) {
            const int col = wN * 64 + nt * 8 + 2 * th;
            if (wN < 2) {
                float b0 = ba[col], b1 = ba[col + 1];
                int n = n0 + row;
                if (n < n_nodes) {
                    size_t i0 = (size_t)n * OC + col;
                    *(float2*)(A + i0) = make_float2(acc[mt][nt][0] + b0,
                                                     acc[mt][nt][1] + b1);
                    *(float2*)(outz + i0) = make_float2(0.f, 0.f);
                }
                n = n0 + row + 8;
                if (n < n_nodes) {
                    size_t i1 = (size_t)n * OC + col;
                    *(float2*)(A + i1) = make_float2(acc[mt][nt][2] + b0,
                                                     acc[mt][nt][3] + b1);
                    *(float2*)(outz + i1) = make_float2(0.f, 0.f);
                }
            } else {
                const int oc = col - 128;
                int n = n0 + row;
                if (n < n_nodes) {
                    __half2 h = __floats2half2_rn(acc[mt][nt][0], acc[mt][nt][1]);
                    *(__half2*)(Bh + (size_t)n * OC + oc) = h;
                }
                n = n0 + row + 8;
                if (n < n_nodes) {
                    __half2 h = __floats2half2_rn(acc[mt][nt][2], acc[mt][nt][3]);
                    *(__half2*)(Bh + (size_t)n * OC + oc) = h;
                }
            }
        }
    }
}

// ---------------------------------------------------------------------------
// Edge kernel (mma.sync fp16 m16n8k16, sorted edges, 2 CTAs/SM).
// A rows deduplicated per segment: staged once to smem (As, <=64 rows;
// global fallback beyond), H computed from smem A + gathered fp16 B.
// Region liveness overlap: H [0,34816) dies at MMA end; As [34816,68608)
// dies when H is built; msg [0,67584) written after MMA over both.
// ---------------------------------------------------------------------------
#define HP   132   // msg row stride (fp32 words)
#define AP   132   // As row stride (fp32)
#define HHW  68    // H row stride in 32-bit words

#define SM_H     0                          // 128*68*4  = 34816
#define SM_AS    34816                      // 64*132*4  = 33792 -> ends 68608
#define SM_SDST  68608                      // int[128]
#define SM_SSRC  (SM_SDST + 512)
#define SM_ESEG  (SM_SSRC + 512)            // int[128]
#define SM_SEGS  (SM_ESEG + 512)            // int[136]
#define SM_SEGN  (SM_SEGS + 544)
#define SM_BB    (SM_SEGN + 512)
#define SM_WC    (SM_BB + 512)
#define SM_NSEG  (SM_WC + 32)
#define SM_TOTAL (SM_NSEG + 16)             // 71760; x2 CTAs = 143.5K, L1 ~84K

__global__ __launch_bounds__(256, 2)
void edge_mma_kernel(const float4* __restrict__ nodeA,
                     const uint4*  __restrict__ nodeBh,
                     const int* __restrict__ ssrc_g,
                     const int* __restrict__ sdst_g,
                     const uint4* __restrict__ wbph,
                     const float* __restrict__ bb,
                     float* __restrict__ out,
                     int E)
{
    extern __shared__ __align__(16) char smem[];
    const int tid  = threadIdx.x;
    const int wid  = tid >> 5;
    const int lane = tid & 31;
    const unsigned FULL = 0xffffffffu;

    uint32_t* Hw   = (uint32_t*)(smem + SM_H);
    float*    As   = (float*)(smem + SM_AS);
    float*    msg  = (float*)(smem + SM_H);      // post-MMA, overlays H+As
    int*      sdst = (int*)(smem + SM_SDST);
    int*      ssrc = (int*)(smem + SM_SSRC);
    int*      eseg = (int*)(smem + SM_ESEG);
    int*      segs = (int*)(smem + SM_SEGS);
    int*      segn = (int*)(smem + SM_SEGN);
    float*    bbs  = (float*)(smem + SM_BB);
    int*      swc  = (int*)(smem + SM_WC);
    int*      snseg= (int*)(smem + SM_NSEG);

    if (tid < 128) bbs[tid] = bb[tid];

    const int ntiles = (E + 127) >> 7;
    const int wM = wid & 3;
    const int wN = wid >> 2;

    const int lm_m   = lane >> 3;
    const int lm_row = (lane & 7) + ((lm_m & 1) << 3);
    const int lm_cw  = (lm_m >> 1) * 4;
    uint32_t lm_addr[2];
#pragma unroll
    for (int mt = 0; mt < 2; mt++)
        lm_addr[mt] = smem_u32(Hw + (wM * 32 + mt * 16 + lm_row) * HHW + lm_cw);

    for (int t = blockIdx.x; t < ntiles; t += gridDim.x) {
        const int e0  = t << 7;
        const int cnt = min(128, E - e0);

        if (tid < 128) {
            sdst[tid] = (tid < cnt) ? sdst_g[e0 + tid] : -1;
            ssrc[tid] = (tid < cnt) ? ssrc_g[e0 + tid] : 0;
        }
        __syncthreads();                                          // S1

        int head = 0; unsigned bm = 0;
        if (tid < 128) {
            head = (tid < cnt) && (tid == 0 || sdst[tid] != sdst[tid - 1]);
            bm = __ballot_sync(FULL, head);
            if (lane == 0) swc[wid] = __popc(bm);
        }
        __syncthreads();                                          // S2
        if (tid == 0) {
            int s = 0;
            for (int w = 0; w < 4; w++) { swc[4 + w] = s; s += swc[w]; }
            snseg[0] = s;
            segs[s]  = cnt;
        }
        __syncthreads();                                          // S3
        if (tid < 128) {
            int incl = swc[4 + wid] + __popc(bm << (31 - lane));
            eseg[tid] = incl - 1;
            if (head) { segs[incl - 1] = tid; segn[incl - 1] = sdst[tid]; }
        }
        __syncthreads();                                          // S4

        // stage unique A rows (one per segment, capped at 64)
        {
            const int nstage = min(snseg[0], 64);
            for (int i = tid; i < (nstage << 5); i += 256) {
                int s = i >> 5, q = i & 31;
                *(float4*)(As + s * AP + (q << 2)) =
                    nodeA[(size_t)segn[s] * 32 + q];
            }
        }
        __syncthreads();                                          // S5

        // H[e][k] = fp16(relu(As[seg] + Bh[src]))
        {
            const int e    = tid >> 1;
            const int half = tid & 1;
            uint4* hrow = (uint4*)Hw + e * (HHW / 4) + half * 8;
            if (e < cnt) {
                const int sid = eseg[e];
                const uint4* brow = nodeBh + (size_t)ssrc[e] * 16 + half * 8;
                if (sid < 64) {
                    const float* arow = As + sid * AP + half * 64;
#pragma unroll
                    for (int m = 0; m < 8; m++) {
                        float4 a0 = *(const float4*)(arow + m * 8);
                        float4 a1 = *(const float4*)(arow + m * 8 + 4);
                        uint4  bv = brow[m];
                        float2 f0 = __half22float2(*(__half2*)&bv.x);
                        float2 f1 = __half22float2(*(__half2*)&bv.y);
                        float2 f2 = __half22float2(*(__half2*)&bv.z);
                        float2 f3 = __half22float2(*(__half2*)&bv.w);
                        uint4 w;
                        w.x = pack_h2(fmaxf(a0.x + f0.x, 0.f), fmaxf(a0.y + f0.y, 0.f));
                        w.y = pack_h2(fmaxf(a0.z + f1.x, 0.f), fmaxf(a0.w + f1.y, 0.f));
                        w.z = pack_h2(fmaxf(a1.x + f2.x, 0.f), fmaxf(a1.y + f2.y, 0.f));
                        w.w = pack_h2(fmaxf(a1.z + f3.x, 0.f), fmaxf(a1.w + f3.y, 0.f));
                        hrow[m] = w;
                    }
                } else {
                    const float4* arow = nodeA + (size_t)sdst[e] * 32 + half * 16;
#pragma unroll
                    for (int m = 0; m < 8; m++) {
                        float4 a0 = arow[2 * m];
                        float4 a1 = arow[2 * m + 1];
                        uint4  bv = brow[m];
                        float2 f0 = __half22float2(*(__half2*)&bv.x);
                        float2 f1 = __half22float2(*(__half2*)&bv.y);
                        float2 f2 = __half22float2(*(__half2*)&bv.z);
                        float2 f3 = __half22float2(*(__half2*)&bv.w);
                        uint4 w;
                        w.x = pack_h2(fmaxf(a0.x + f0.x, 0.f), fmaxf(a0.y + f0.y, 0.f));
                        w.y = pack_h2(fmaxf(a0.z + f1.x, 0.f), fmaxf(a0.w + f1.y, 0.f));
                        w.z = pack_h2(fmaxf(a1.x + f2.x, 0.f), fmaxf(a1.y + f2.y, 0.f));
                        w.w = pack_h2(fmaxf(a1.z + f3.x, 0.f), fmaxf(a1.w + f3.y, 0.f));
                        hrow[m] = w;
                    }
                }
            } else {
#pragma unroll
                for (int m = 0; m < 8; m++)
                    hrow[m] = make_uint4(0u, 0u, 0u, 0u);
            }
        }
        __syncthreads();                                          // S6

        // MMA: warp tile 32 edges x 64 outs
        float acc[2][8][4];
#pragma unroll
        for (int mt = 0; mt < 2; mt++)
#pragma unroll
            for (int nt = 0; nt < 8; nt++)
#pragma unroll
                for (int r = 0; r < 4; r++) acc[mt][nt][r] = 0.f;

        const int g = lane >> 2, th = lane & 3;
        const uint4* wrow = wbph + (size_t)wN * 1024 + lane;
#pragma unroll
        for (int kk = 0; kk < 8; kk++) {
            uint32_t a[2][4];
#pragma unroll
            for (int mt = 0; mt < 2; mt++)
                LDMATRIX_X4(a[mt][0], a[mt][1], a[mt][2], a[mt][3],
                            lm_addr[mt] + kk * 32);
#pragma unroll
            for (int p = 0; p < 4; p++) {
                uint4 bp = wrow[kk * 128 + p * 32];
#pragma unroll
                for (int mt = 0; mt < 2; mt++) {
                    mma_f16(acc[mt][2 * p],     a[mt], bp.x, bp.y);
                    mma_f16(acc[mt][2 * p + 1], a[mt], bp.z, bp.w);
                }
            }
        }
        __syncthreads();                                          // S7

        // store D -> msg[e][c] (overlays H/As, both dead now)
#pragma unroll
        for (int mt = 0; mt < 2; mt++) {
            const int row = wM * 32 + mt * 16 + g;
#pragma unroll
            for (int nt = 0; nt < 8; nt++) {
                const int col = wN * 64 + nt * 8 + 2 * th;
                *(float2*)(msg + row * HP + col) =
                    make_float2(acc[mt][nt][0], acc[mt][nt][1]);
                *(float2*)(msg + (row + 8) * HP + col) =
                    make_float2(acc[mt][nt][2], acc[mt][nt][3]);
            }
        }
        __syncthreads();                                          // S8

        // segmented max + writeback
        {
            const int nseg = snseg[0];
            for (int i = tid; i < nseg * 128; i += 256) {
                const int c = i & 127;
                const int s = i >> 7;
                const int st = segs[s], en = segs[s + 1];
                float m = -3.4e38f;
                for (int e = st; e < en; e++)
                    m = fmaxf(m, msg[e * HP + c]);
                m += bbs[c];
                float* o = out + (size_t)segn[s] * OC + c;
                if (st == 0 || en == cnt) {
                    atomicMax((int*)o, __float_as_int(m));
                } else {
                    *o = fmaxf(m, 0.f);
                }
            }
        }
        __syncthreads();                                          // S9
    }
}

// ---------------------------------------------------------------------------
// Final: concat(x2,x4,x6) [384] -> maxpool(24) -> 16 -> @ fw + fb
// ---------------------------------------------------------------------------
__global__ __launch_bounds__(256)
void final_kernel(const float* __restrict__ x2,
                  const float* __restrict__ x4,
                  const float* __restrict__ x6,
                  const float* __restrict__ fw,
                  const float* __restrict__ fb,
                  float* __restrict__ out,
                  int n_nodes)
{
    const unsigned FULL = 0xffffffffu;
    const int lane = threadIdx.x & 31;
    const int warp = blockIdx.x * (blockDim.x >> 5) + (threadIdx.x >> 5);
    const int nw   = gridDim.x * (blockDim.x >> 5);

    for (int n = warp; n < n_nodes; n += nw) {
        float m = -3.4e38f;
        int idx0 = lane * 12;
#pragma unroll
        for (int i = 0; i < 12; i++) {
            int idx = idx0 + i;
            float v;
            if (idx < 128)       v = x2[(size_t)n * OC + idx];
            else if (idx < 256)  v = x4[(size_t)n * OC + idx - 128];
            else                 v = x6[(size_t)n * OC + idx - 256];
            m = fmaxf(m, v);
        }
        float mm = fmaxf(m, __shfl_xor_sync(FULL, m, 1));
        float part = ((lane & 1) == 0) ? mm * fw[lane >> 1] : 0.f;
#pragma unroll
        for (int off = 16; off >= 1; off >>= 1)
            part += __shfl_xor_sync(FULL, part, off);
        if (lane == 0) out[n] = part + fb[0];
    }
}

// ---------------------------------------------------------------------------
extern "C" void kernel_launch(void* const* d_in, const int* in_sizes, int n_in,
                              void* d_out, int out_size)
{
    const float* x   = (const float*)d_in[0];
    const void*  ei  = d_in[1];
    const float* w1a = (const float*)d_in[2];  const float* b1a = (const float*)d_in[3];
    const float* w1b = (const float*)d_in[4];  const float* b1b = (const float*)d_in[5];
    const float* w2a = (const float*)d_in[6];  const float* b2a = (const float*)d_in[7];
    const float* w2b = (const float*)d_in[8];  const float* b2b = (const float*)d_in[9];
    const float* w3a = (const float*)d_in[10]; const float* b3a = (const float*)d_in[11];
    const float* w3b = (const float*)d_in[12]; const float* b3b = (const float*)d_in[13];
    const float* fw  = (const float*)d_in[14]; const float* fb  = (const float*)d_in[15];
    float* out = (float*)d_out;

    const int       N = in_sizes[0] / 24;
    const long long E = in_sizes[1] / 2;

    float *A, *X2, *X4, *X6;
    __half *Bh;
    int *deg, *off, *cur, *ssrc, *sdst;
    uint4 *wbph;
    uint2 *wap;
    cudaGetSymbolAddress((void**)&A,    g_A);
    cudaGetSymbolAddress((void**)&Bh,   g_Bh);
    cudaGetSymbolAddress((void**)&X2,   g_x2);
    cudaGetSymbolAddress((void**)&X4,   g_x4);
    cudaGetSymbolAddress((void**)&X6,   g_x6);
    cudaGetSymbolAddress((void**)&deg,  g_deg);
    cudaGetSymbolAddress((void**)&off,  g_off);
    cudaGetSymbolAddress((void**)&cur,  g_cur);
    cudaGetSymbolAddress((void**)&ssrc, g_ssrc);
    cudaGetSymbolAddress((void**)&sdst, g_sdst);
    cudaGetSymbolAddress((void**)&wbph, g_wbph);
    cudaGetSymbolAddress((void**)&wap,  g_wap);

    cudaFuncSetAttribute(edge_mma_kernel,
                         cudaFuncAttributeMaxDynamicSharedMemorySize, SM_TOTAL);

    // ---- edge-index width + counting sort by dst ----
    detect_idx_kernel<<<1, 256>>>((const int*)ei);
    cudaMemsetAsync(deg, 0, (size_t)N * sizeof(int));
    cudaMemsetAsync(cur, 0, (size_t)N * sizeof(int));
    hist_kernel<<<512, 256>>>(ei, E, deg);
    scan_kernel<<<1, 1024>>>(deg, off, N);
    scatter_kernel<<<512, 256>>>(ei, E, off, cur, ssrc, sdst);

    // ---- weight prep ----
    prep_wh_kernel<<<8, 256>>>(w1b, wbph);
    prep_wh_kernel<<<8, 256>>>(w2b, wbph + 2048);
    prep_wh_kernel<<<8, 256>>>(w3b, wbph + 4096);
    prep_wa_kernel<<<64, 256>>>(w2a, wap);
    prep_wa_kernel<<<64, 256>>>(w3a, wap + 16384);

    const int node1_grid = (N + 15) / 16;
    const int nodem_grid = (N + 63) / 64;
    const int edge_grid  = 296;   // 2 CTAs/SM

    // Layer 1 (C = 24, scalar)
    node_kernel<24, 16><<<node1_grid, 128>>>(x, w1a, b1a, A, Bh, X2, N);
    edge_mma_kernel<<<edge_grid, 256, SM_TOTAL>>>((const float4*)A, (const uint4*)Bh,
        ssrc, sdst, wbph, b1b, X2, (int)E);
    // Layer 2 (C = 128, tf32 mma)
    node_mma_kernel<<<nodem_grid, 256>>>(X2, wap, b2a, A, Bh, X4, N);
    edge_mma_kernel<<<edge_grid, 256, SM_TOTAL>>>((const float4*)A, (const uint4*)Bh,
        ssrc, sdst, wbph + 2048, b2b, X4, (int)E);
    // Layer 3 (C = 128, tf32 mma)
    node_mma_kernel<<<nodem_grid, 256>>>(X4, wap + 16384, b3a, A, Bh, X6, N);
    edge_mma_kernel<<<edge_grid, 256, SM_TOTAL>>>((const float4*)A, (const uint4*)Bh,
        ssrc, sdst, wbph + 4096, b3b, X6, (int)E);

    // Pool + final linear
    final_kernel<<<(N + 7) / 8, 256>>>(X2, X4, X6, fw, fb, out, N);
}

// round 15
// speedup vs baseline: 2.4922x; 1.0273x over previous
#include <cuda_runtime.h>
#include <cuda_fp16.h>
#include <math.h>
#include <stdint.h>

#define NN   100000
#define OC   128
#define MAXE 1600000

// ---------------------------------------------------------------------------
// Device scratch
// ---------------------------------------------------------------------------
__device__ __align__(16) float  g_A [(size_t)NN * OC];
__device__ __align__(16) __half g_Bh[(size_t)NN * OC];
__device__ __align__(16) float  g_x2[(size_t)NN * OC];
__device__ __align__(16) float  g_x4[(size_t)NN * OC];
__device__ __align__(16) float  g_x6[(size_t)NN * OC];

__device__ int g_deg[NN];
__device__ int g_off[NN + 1];
__device__ int g_cur[NN];
__device__ int g_ssrc[MAXE];
__device__ int g_sdst[MAXE];
// fp16 edge-W fragments per layer: [wN(2)][kk(8)][p(4)][lane(32)] uint4
__device__ __align__(16) uint4 g_wbph[3][2048];
// tf32 node-W fragments (layers 2,3): [wN(4)][kk(16)][nt(8)][lane(32)] uint2
__device__ __align__(16) uint2 g_wap[2][16384];
__device__ int g_idx64;

// ---------------------------------------------------------------------------
// helpers
// ---------------------------------------------------------------------------
__device__ __forceinline__ uint32_t pack_h2(float lo, float hi) {
    __half2 h = __floats2half2_rn(lo, hi);
    return *(uint32_t*)&h;
}
__device__ __forceinline__ uint32_t f2tf32(float f) {
    uint32_t r;
    asm("cvt.rna.tf32.f32 %0, %1;" : "=r"(r) : "f"(f));
    return r;
}
// relu(a + b) in packed half2
__device__ __forceinline__ uint32_t h2_addrelu(uint32_t a, uint32_t b) {
    __half2 z = __float2half2_rn(0.f);
    __half2 r = __hmax2(__hadd2(*(__half2*)&a, *(__half2*)&b), z);
    return *(uint32_t*)&r;
}

__device__ __forceinline__ void mma_f16(float* d, const uint32_t* a,
                                        uint32_t b0, uint32_t b1) {
    asm volatile(
        "mma.sync.aligned.m16n8k16.row.col.f32.f16.f16.f32 "
        "{%0,%1,%2,%3}, {%4,%5,%6,%7}, {%8,%9}, {%0,%1,%2,%3};"
        : "+f"(d[0]), "+f"(d[1]), "+f"(d[2]), "+f"(d[3])
        : "r"(a[0]), "r"(a[1]), "r"(a[2]), "r"(a[3]), "r"(b0), "r"(b1));
}
__device__ __forceinline__ void mma_tf32(float* d, const uint32_t* a,
                                         uint32_t b0, uint32_t b1) {
    asm volatile(
        "mma.sync.aligned.m16n8k8.row.col.f32.tf32.tf32.f32 "
        "{%0,%1,%2,%3}, {%4,%5,%6,%7}, {%8,%9}, {%0,%1,%2,%3};"
        : "+f"(d[0]), "+f"(d[1]), "+f"(d[2]), "+f"(d[3])
        : "r"(a[0]), "r"(a[1]), "r"(a[2]), "r"(a[3]), "r"(b0), "r"(b1));
}

__device__ __forceinline__ uint32_t smem_u32(const void* p) {
    uint32_t a;
    asm("{ .reg .u64 t; cvta.to.shared.u64 t, %1; cvt.u32.u64 %0, t; }"
        : "=r"(a) : "l"(p));
    return a;
}

#define LDMATRIX_X4(r0, r1, r2, r3, addr) \
    asm volatile("ldmatrix.sync.aligned.m8n8.x4.shared.b16 {%0,%1,%2,%3}, [%4];" \
                 : "=r"(r0), "=r"(r1), "=r"(r2), "=r"(r3) : "r"(addr))

// ---------------------------------------------------------------------------
// Index-width detection (int32 vs int64 edge_index)
// ---------------------------------------------------------------------------
__global__ void detect_idx_kernel(const int* __restrict__ ei)
{
    __shared__ int any;
    if (threadIdx.x == 0) any = 0;
    __syncthreads();
    for (int i = threadIdx.x; i < 2048; i += blockDim.x)
        if (ei[2 * i + 1] != 0) any = 1;
    __syncthreads();
    if (threadIdx.x == 0) g_idx64 = (any == 0) ? 1 : 0;
}

// ---------------------------------------------------------------------------
// Counting sort by dst
// ---------------------------------------------------------------------------
__global__ void hist_kernel(const void* __restrict__ ei, long long E, int* __restrict__ deg)
{
    const int idx64 = g_idx64;
    long long i = (long long)blockIdx.x * blockDim.x + threadIdx.x;
    const long long stride = (long long)gridDim.x * blockDim.x;
    for (; i < E; i += stride) {
        int d = idx64 ? (int)((const long long*)ei)[E + i] : ((const int*)ei)[E + i];
        atomicAdd(&deg[d], 1);
    }
}

// Warp-shuffle scan: 4 barriers per 1024-chunk.
__global__ void scan_kernel(const int* __restrict__ deg, int* __restrict__ off, int n)
{
    const unsigned FULL = 0xffffffffu;
    __shared__ int wsum[32];
    __shared__ int carry_s;
    const int tid  = threadIdx.x;
    const int lane = tid & 31;
    const int wid  = tid >> 5;
    if (tid == 0) carry_s = 0;
    __syncthreads();
    for (int base = 0; base < n; base += 1024) {
        int i = base + tid;
        int v = (i < n) ? deg[i] : 0;
        int s = v;
#pragma unroll
        for (int d = 1; d < 32; d <<= 1) {
            int t = __shfl_up_sync(FULL, s, d);
            if (lane >= d) s += t;
        }
        if (lane == 31) wsum[wid] = s;
        __syncthreads();
        if (wid == 0) {
            int w = wsum[lane];
#pragma unroll
            for (int d = 1; d < 32; d <<= 1) {
                int t = __shfl_up_sync(FULL, w, d);
                if (lane >= d) w += t;
            }
            wsum[lane] = w;
        }
        __syncthreads();
        int carry = carry_s;
        if (i < n) off[i] = carry + (wid ? wsum[wid - 1] : 0) + s - v;
        __syncthreads();
        if (tid == 0) carry_s = carry + wsum[31];
        __syncthreads();
    }
    if (threadIdx.x == 0) off[n] = carry_s;
}

__global__ void scatter_kernel(const void* __restrict__ ei, long long E,
                               const int* __restrict__ off, int* __restrict__ cur,
                               int* __restrict__ ssrc, int* __restrict__ sdst)
{
    const int idx64 = g_idx64;
    long long i = (long long)blockIdx.x * blockDim.x + threadIdx.x;
    const long long stride = (long long)gridDim.x * blockDim.x;
    for (; i < E; i += stride) {
        int s, d;
        if (idx64) { s = (int)((const long long*)ei)[i]; d = (int)((const long long*)ei)[E + i]; }
        else       { s = ((const int*)ei)[i];            d = ((const int*)ei)[E + i]; }
        int p = off[d] + atomicAdd(&cur[d], 1);
        ssrc[p] = s;
        sdst[p] = d;
    }
}

// ---------------------------------------------------------------------------
// Pack wb [K=128][N=128] -> fp16 B fragments for m16n8k16 (edge GEMM)
// ---------------------------------------------------------------------------
__global__ void prep_wh_kernel(const float* __restrict__ wb, uint4* __restrict__ outp)
{
    int idx = blockIdx.x * blockDim.x + threadIdx.x;
    if (idx >= 2048) return;
    int lane = idx & 31;
    int p    = (idx >> 5) & 3;
    int kk   = (idx >> 7) & 7;
    int wN   = idx >> 10;
    int g  = lane >> 2, th = lane & 3;
    int n0 = wN * 64 + p * 16 + g;
    int n1 = n0 + 8;
    int k0 = kk * 16 + 2 * th;
    uint4 v;
    v.x = pack_h2(wb[k0 * 128 + n0],       wb[(k0 + 1) * 128 + n0]);
    v.y = pack_h2(wb[(k0 + 8) * 128 + n0], wb[(k0 + 9) * 128 + n0]);
    v.z = pack_h2(wb[k0 * 128 + n1],       wb[(k0 + 1) * 128 + n1]);
    v.w = pack_h2(wb[(k0 + 8) * 128 + n1], wb[(k0 + 9) * 128 + n1]);
    outp[idx] = v;
}

// ---------------------------------------------------------------------------
// Pack wa [2*128][128] -> tf32 fragments for combined node GEMM (m16n8k8).
// idx = wN*4096 + kk*256 + nt*32 + lane (wN at bit 12)
// ---------------------------------------------------------------------------
__global__ void prep_wa_kernel(const float* __restrict__ wa, uint2* __restrict__ outp)
{
    int idx = blockIdx.x * blockDim.x + threadIdx.x;
    if (idx >= 16384) return;
    int lane = idx & 31;
    int nt   = (idx >> 5) & 7;
    int kk   = (idx >> 8) & 15;
    int wN   = idx >> 12;
    int g = lane >> 2, th = lane & 3;
    int n  = wN * 64 + nt * 8 + g;
    int k0 = kk * 8 + th;
    float w0, w1;
    if (n < 128) {
        w0 = wa[k0 * 128 + n]       - wa[(128 + k0) * 128 + n];
        w1 = wa[(k0 + 4) * 128 + n] - wa[(132 + k0) * 128 + n];
    } else {
        int nn = n - 128;
        w0 = wa[(128 + k0) * 128 + nn];
        w1 = wa[(132 + k0) * 128 + nn];
    }
    outp[idx] = make_uint2(f2tf32(w0), f2tf32(w1));
}

// ---------------------------------------------------------------------------
// Scalar node transform (layer 1 only, C = 24)
// ---------------------------------------------------------------------------
template<int C, int NPB>
__global__ __launch_bounds__(128)
void node_kernel(const float* __restrict__ x,
                 const float* __restrict__ wa,
                 const float* __restrict__ ba,
                 float* __restrict__ A,
                 __half* __restrict__ Bh,
                 float* __restrict__ outz,
                 int n_nodes)
{
    __shared__ float xs[NPB * C];
    const int n0  = blockIdx.x * NPB;
    const int tid = threadIdx.x;

    for (int i = tid; i < NPB * C; i += 128) {
        int nn = i / C, c = i % C;
        int n = n0 + nn;
        xs[i] = (n < n_nodes) ? x[(size_t)n * C + c] : 0.f;
    }
    __syncthreads();

    float a[NPB], b[NPB];
#pragma unroll
    for (int t = 0; t < NPB; t++) { a[t] = 0.f; b[t] = 0.f; }

    const int o = tid;
#pragma unroll 4
    for (int c = 0; c < C; c++) {
        float wtop = wa[(size_t)c       * OC + o];
        float wbot = wa[(size_t)(C + c) * OC + o];
        float wd   = wtop - wbot;
#pragma unroll
        for (int t = 0; t < NPB; t++) {
            float xv = xs[t * C + c];
            a[t] += xv * wd;
            b[t] += xv * wbot;
        }
    }
    float bao = ba[o];
#pragma unroll
    for (int t = 0; t < NPB; t++) {
        int n = n0 + t;
        if (n < n_nodes) {
            size_t idx = (size_t)n * OC + o;
            A[idx]    = a[t] + bao;
            Bh[idx]   = __float2half(b[t]);
            outz[idx] = 0.f;
        }
    }
}

// ---------------------------------------------------------------------------
// Tensor node transform (C = 128 layers), tf32 m16n8k8, 64 nodes x 256 outs.
// ---------------------------------------------------------------------------
#define NXS 132

__global__ __launch_bounds__(256, 2)
void node_mma_kernel(const float* __restrict__ x,
                     const uint2* __restrict__ wap,
                     const float* __restrict__ ba,
                     float* __restrict__ A,
                     __half* __restrict__ Bh,
                     float* __restrict__ outz,
                     int n_nodes)
{
    __shared__ uint32_t xs[64 * NXS];
    const int tid  = threadIdx.x;
    const int wid  = tid >> 5;
    const int lane = tid & 31;
    const int n0   = blockIdx.x * 64;

    for (int i = tid; i < 64 * 32; i += 256) {
        int r = i >> 5, q = i & 31;
        uint4 v;
        if (n0 + r < n_nodes) {
            float4 f = *(const float4*)(x + (size_t)(n0 + r) * 128 + q * 4);
            v.x = f2tf32(f.x); v.y = f2tf32(f.y);
            v.z = f2tf32(f.z); v.w = f2tf32(f.w);
        } else {
            v = make_uint4(0u, 0u, 0u, 0u);
        }
        *(uint4*)(xs + r * NXS + q * 4) = v;
    }
    __syncthreads();

    const int wM = wid & 1;
    const int wN = wid >> 1;
    const int g = lane >> 2, th = lane & 3;

    float acc[2][8][4];
#pragma unroll
    for (int mt = 0; mt < 2; mt++)
#pragma unroll
        for (int nt = 0; nt < 8; nt++)
#pragma unroll
            for (int r = 0; r < 4; r++) acc[mt][nt][r] = 0.f;

    const uint2* wrow = wap + (size_t)wN * 4096 + lane;
#pragma unroll 4
    for (int kk = 0; kk < 16; kk++) {
        uint32_t a[2][4];
#pragma unroll
        for (int mt = 0; mt < 2; mt++) {
            const uint32_t* base = xs + (wM * 32 + mt * 16 + g) * NXS + kk * 8 + th;
            a[mt][0] = base[0];
            a[mt][1] = base[8 * NXS];
            a[mt][2] = base[4];
            a[mt][3] = base[8 * NXS + 4];
        }
#pragma unroll
        for (int nt = 0; nt < 8; nt++) {
            uint2 bp = wrow[(kk * 8 + nt) * 32];
#pragma unroll
            for (int mt = 0; mt < 2; mt++)
                mma_tf32(acc[mt][nt], a[mt], bp.x, bp.y);
        }
    }

#pragma unroll
    for (int mt = 0; mt < 2; mt++) {
        const int row = wM * 32 + mt * 16 + g;
#pragma unroll
        for (int nt = 0; nt < 8; nt++) {
            const int col = wN * 64 + nt * 8 + 2 * th;
            if (wN < 2) {
                float b0 = ba[col], b1 = ba[col + 1];
                int n = n0 + row;
                if (n < n_nodes) {
                    size_t i0 = (size_t)n * OC + col;
                    *(float2*)(A + i0) = make_float2(acc[mt][nt][0] + b0,
                                                     acc[mt][nt][1] + b1);
                    *(float2*)(outz + i0) = make_float2(0.f, 0.f);
                }
                n = n0 + row + 8;
                if (n < n_nodes) {
                    size_t i1 = (size_t)n * OC + col;
                    *(float2*)(A + i1) = make_float2(acc[mt][nt][2] + b0,
                                                     acc[mt][nt][3] + b1);
                    *(float2*)(outz + i1) = make_float2(0.f, 0.f);
                }
            } else {
                const int oc = col - 128;
                int n = n0 + row;
                if (n < n_nodes) {
                    __half2 h = __floats2half2_rn(acc[mt][nt][0], acc[mt][nt][1]);
                    *(__half2*)(Bh + (size_t)n * OC + oc) = h;
                }
                n = n0 + row + 8;
                if (n < n_nodes) {
                    __half2 h = __floats2half2_rn(acc[mt][nt][2], acc[mt][nt][3]);
                    *(__half2*)(Bh + (size_t)n * OC + oc) = h;
                }
            }
        }
    }
}

// ---------------------------------------------------------------------------
// Edge kernel (mma.sync fp16 m16n8k16, sorted edges, 2 CTAs/SM).
// Unique A rows staged ONCE per tile as half2 (one fp32->fp16 conversion per
// unique row); H-build is pure half2: HADD2 + HMAX2. Global-fp32 fallback
// for tiles with >64 segments.
// ---------------------------------------------------------------------------
#define HP   132   // msg row stride (fp32 words)
#define AHW  68    // As_h2 row stride (uint32 half2 words; 64 data words)
#define HHW  68    // H row stride in 32-bit words

#define SM_H     0                          // 128*68*4  = 34816
#define SM_AS    34816                      // 64*68*4 = 17408 (region to 68608)
#define SM_SDST  68608                      // int[128]
#define SM_SSRC  (SM_SDST + 512)
#define SM_ESEG  (SM_SSRC + 512)            // int[128]
#define SM_SEGS  (SM_ESEG + 512)            // int[136]
#define SM_SEGN  (SM_SEGS + 544)
#define SM_BB    (SM_SEGN + 512)
#define SM_WC    (SM_BB + 512)
#define SM_NSEG  (SM_WC + 32)
#define SM_TOTAL (SM_NSEG + 16)             // 71760

__global__ __launch_bounds__(256, 2)
void edge_mma_kernel(const float4* __restrict__ nodeA,
                     const uint4*  __restrict__ nodeBh,
                     const int* __restrict__ ssrc_g,
                     const int* __restrict__ sdst_g,
                     const uint4* __restrict__ wbph,
                     const float* __restrict__ bb,
                     float* __restrict__ out,
                     int E)
{
    extern __shared__ __align__(16) char smem[];
    const int tid  = threadIdx.x;
    const int wid  = tid >> 5;
    const int lane = tid & 31;
    const unsigned FULL = 0xffffffffu;

    uint32_t* Hw   = (uint32_t*)(smem + SM_H);
    uint32_t* Ash  = (uint32_t*)(smem + SM_AS);  // half2 rows
    float*    msg  = (float*)(smem + SM_H);      // post-MMA, overlays H+As
    int*      sdst = (int*)(smem + SM_SDST);
    int*      ssrc = (int*)(smem + SM_SSRC);
    int*      eseg = (int*)(smem + SM_ESEG);
    int*      segs = (int*)(smem + SM_SEGS);
    int*      segn = (int*)(smem + SM_SEGN);
    float*    bbs  = (float*)(smem + SM_BB);
    int*      swc  = (int*)(smem + SM_WC);
    int*      snseg= (int*)(smem + SM_NSEG);

    if (tid < 128) bbs[tid] = bb[tid];

    const int ntiles = (E + 127) >> 7;
    const int wM = wid & 3;
    const int wN = wid >> 2;

    const int lm_m   = lane >> 3;
    const int lm_row = (lane & 7) + ((lm_m & 1) << 3);
    const int lm_cw  = (lm_m >> 1) * 4;
    uint32_t lm_addr[2];
#pragma unroll
    for (int mt = 0; mt < 2; mt++)
        lm_addr[mt] = smem_u32(Hw + (wM * 32 + mt * 16 + lm_row) * HHW + lm_cw);

    for (int t = blockIdx.x; t < ntiles; t += gridDim.x) {
        const int e0  = t << 7;
        const int cnt = min(128, E - e0);

        if (tid < 128) {
            sdst[tid] = (tid < cnt) ? sdst_g[e0 + tid] : -1;
            ssrc[tid] = (tid < cnt) ? ssrc_g[e0 + tid] : 0;
        }
        __syncthreads();                                          // S1

        int head = 0; unsigned bm = 0;
        if (tid < 128) {
            head = (tid < cnt) && (tid == 0 || sdst[tid] != sdst[tid - 1]);
            bm = __ballot_sync(FULL, head);
            if (lane == 0) swc[wid] = __popc(bm);
        }
        __syncthreads();                                          // S2
        if (tid == 0) {
            int s = 0;
            for (int w = 0; w < 4; w++) { swc[4 + w] = s; s += swc[w]; }
            snseg[0] = s;
            segs[s]  = cnt;
        }
        __syncthreads();                                          // S3
        if (tid < 128) {
            int incl = swc[4 + wid] + __popc(bm << (31 - lane));
            eseg[tid] = incl - 1;
            if (head) { segs[incl - 1] = tid; segn[incl - 1] = sdst[tid]; }
        }
        __syncthreads();                                          // S4

        // stage unique A rows as half2 (convert once per unique row)
        {
            const int nstage = min(snseg[0], 64);
            for (int i = tid; i < (nstage << 4); i += 256) {
                int s = i >> 4, q = i & 15;     // q-th uint4 (8 floats -> 4 half2)
                const float4* src = nodeA + (size_t)segn[s] * 32 + q * 2;
                float4 f0 = src[0], f1 = src[1];
                uint4 v;
                v.x = pack_h2(f0.x, f0.y);
                v.y = pack_h2(f0.z, f0.w);
                v.z = pack_h2(f1.x, f1.y);
                v.w = pack_h2(f1.z, f1.w);
                *(uint4*)(Ash + s * AHW + q * 4) = v;
            }
        }
        __syncthreads();                                          // S5

        // H[e][k] = relu_h2(As_h2[seg] + Bh[src])
        {
            const int e    = tid >> 1;
            const int half = tid & 1;
            uint4* hrow = (uint4*)Hw + e * (HHW / 4) + half * 8;
            if (e < cnt) {
                const int sid = eseg[e];
                const uint4* brow = nodeBh + (size_t)ssrc[e] * 16 + half * 8;
                if (sid < 64) {
                    const uint4* arow = (const uint4*)(Ash + sid * AHW) + half * 8;
#pragma unroll
                    for (int m = 0; m < 8; m++) {
                        uint4 av = arow[m];
                        uint4 bv = brow[m];
                        uint4 w;
                        w.x = h2_addrelu(av.x, bv.x);
                        w.y = h2_addrelu(av.y, bv.y);
                        w.z = h2_addrelu(av.z, bv.z);
                        w.w = h2_addrelu(av.w, bv.w);
                        hrow[m] = w;
                    }
                } else {
                    const float4* arow = nodeA + (size_t)sdst[e] * 32 + half * 16;
#pragma unroll
                    for (int m = 0; m < 8; m++) {
                        float4 a0 = arow[2 * m];
                        float4 a1 = arow[2 * m + 1];
                        uint4  bv = brow[m];
                        float2 f0 = __half22float2(*(__half2*)&bv.x);
                        float2 f1 = __half22float2(*(__half2*)&bv.y);
                        float2 f2 = __half22float2(*(__half2*)&bv.z);
                        float2 f3 = __half22float2(*(__half2*)&bv.w);
                        uint4 w;
                        w.x = pack_h2(fmaxf(a0.x + f0.x, 0.f), fmaxf(a0.y + f0.y, 0.f));
                        w.y = pack_h2(fmaxf(a0.z + f1.x, 0.f), fmaxf(a0.w + f1.y, 0.f));
                        w.z = pack_h2(fmaxf(a1.x + f2.x, 0.f), fmaxf(a1.y + f2.y, 0.f));
                        w.w = pack_h2(fmaxf(a1.z + f3.x, 0.f), fmaxf(a1.w + f3.y, 0.f));
                        hrow[m] = w;
                    }
                }
            } else {
#pragma unroll
                for (int m = 0; m < 8; m++)
                    hrow[m] = make_uint4(0u, 0u, 0u, 0u);
            }
        }
        __syncthreads();                                          // S6

        // MMA: warp tile 32 edges x 64 outs
        float acc[2][8][4];
#pragma unroll
        for (int mt = 0; mt < 2; mt++)
#pragma unroll
            for (int nt = 0; nt < 8; nt++)
#pragma unroll
                for (int r = 0; r < 4; r++) acc[mt][nt][r] = 0.f;

        const int g = lane >> 2, th = lane & 3;
        const uint4* wrow = wbph + (size_t)wN * 1024 + lane;
#pragma unroll
        for (int kk = 0; kk < 8; kk++) {
            uint32_t a[2][4];
#pragma unroll
            for (int mt = 0; mt < 2; mt++)
                LDMATRIX_X4(a[mt][0], a[mt][1], a[mt][2], a[mt][3],
                            lm_addr[mt] + kk * 32);
#pragma unroll
            for (int p = 0; p < 4; p++) {
                uint4 bp = wrow[kk * 128 + p * 32];
#pragma unroll
                for (int mt = 0; mt < 2; mt++) {
                    mma_f16(acc[mt][2 * p],     a[mt], bp.x, bp.y);
                    mma_f16(acc[mt][2 * p + 1], a[mt], bp.z, bp.w);
                }
            }
        }
        __syncthreads();                                          // S7

        // store D -> msg[e][c] (overlays H/As, both dead now)
#pragma unroll
        for (int mt = 0; mt < 2; mt++) {
            const int row = wM * 32 + mt * 16 + g;
#pragma unroll
            for (int nt = 0; nt < 8; nt++) {
                const int col = wN * 64 + nt * 8 + 2 * th;
                *(float2*)(msg + row * HP + col) =
                    make_float2(acc[mt][nt][0], acc[mt][nt][1]);
                *(float2*)(msg + (row + 8) * HP + col) =
                    make_float2(acc[mt][nt][2], acc[mt][nt][3]);
            }
        }
        __syncthreads();                                          // S8

        // segmented max + writeback
        {
            const int nseg = snseg[0];
            for (int i = tid; i < nseg * 128; i += 256) {
                const int c = i & 127;
                const int s = i >> 7;
                const int st = segs[s], en = segs[s + 1];
                float m = -3.4e38f;
                for (int e = st; e < en; e++)
                    m = fmaxf(m, msg[e * HP + c]);
                m += bbs[c];
                float* o = out + (size_t)segn[s] * OC + c;
                if (st == 0 || en == cnt) {
                    atomicMax((int*)o, __float_as_int(m));
                } else {
                    *o = fmaxf(m, 0.f);
                }
            }
        }
        __syncthreads();                                          // S9
    }
}

// ---------------------------------------------------------------------------
// Final: concat(x2,x4,x6) [384] -> maxpool(24) -> 16 -> @ fw + fb
// ---------------------------------------------------------------------------
__global__ __launch_bounds__(256)
void final_kernel(const float* __restrict__ x2,
                  const float* __restrict__ x4,
                  const float* __restrict__ x6,
                  const float* __restrict__ fw,
                  const float* __restrict__ fb,
                  float* __restrict__ out,
                  int n_nodes)
{
    const unsigned FULL = 0xffffffffu;
    const int lane = threadIdx.x & 31;
    const int warp = blockIdx.x * (blockDim.x >> 5) + (threadIdx.x >> 5);
    const int nw   = gridDim.x * (blockDim.x >> 5);

    for (int n = warp; n < n_nodes; n += nw) {
        float m = -3.4e38f;
        int idx0 = lane * 12;
#pragma unroll
        for (int i = 0; i < 12; i++) {
            int idx = idx0 + i;
            float v;
            if (idx < 128)       v = x2[(size_t)n * OC + idx];
            else if (idx < 256)  v = x4[(size_t)n * OC + idx - 128];
            else                 v = x6[(size_t)n * OC + idx - 256];
            m = fmaxf(m, v);
        }
        float mm = fmaxf(m, __shfl_xor_sync(FULL, m, 1));
        float part = ((lane & 1) == 0) ? mm * fw[lane >> 1] : 0.f;
#pragma unroll
        for (int off = 16; off >= 1; off >>= 1)
            part += __shfl_xor_sync(FULL, part, off);
        if (lane == 0) out[n] = part + fb[0];
    }
}

// ---------------------------------------------------------------------------
extern "C" void kernel_launch(void* const* d_in, const int* in_sizes, int n_in,
                              void* d_out, int out_size)
{
    const float* x   = (const float*)d_in[0];
    const void*  ei  = d_in[1];
    const float* w1a = (const float*)d_in[2];  const float* b1a = (const float*)d_in[3];
    const float* w1b = (const float*)d_in[4];  const float* b1b = (const float*)d_in[5];
    const float* w2a = (const float*)d_in[6];  const float* b2a = (const float*)d_in[7];
    const float* w2b = (const float*)d_in[8];  const float* b2b = (const float*)d_in[9];
    const float* w3a = (const float*)d_in[10]; const float* b3a = (const float*)d_in[11];
    const float* w3b = (const float*)d_in[12]; const float* b3b = (const float*)d_in[13];
    const float* fw  = (const float*)d_in[14]; const float* fb  = (const float*)d_in[15];
    float* out = (float*)d_out;

    const int       N = in_sizes[0] / 24;
    const long long E = in_sizes[1] / 2;

    float *A, *X2, *X4, *X6;
    __half *Bh;
    int *deg, *off, *cur, *ssrc, *sdst;
    uint4 *wbph;
    uint2 *wap;
    cudaGetSymbolAddress((void**)&A,    g_A);
    cudaGetSymbolAddress((void**)&Bh,   g_Bh);
    cudaGetSymbolAddress((void**)&X2,   g_x2);
    cudaGetSymbolAddress((void**)&X4,   g_x4);
    cudaGetSymbolAddress((void**)&X6,   g_x6);
    cudaGetSymbolAddress((void**)&deg,  g_deg);
    cudaGetSymbolAddress((void**)&off,  g_off);
    cudaGetSymbolAddress((void**)&cur,  g_cur);
    cudaGetSymbolAddress((void**)&ssrc, g_ssrc);
    cudaGetSymbolAddress((void**)&sdst, g_sdst);
    cudaGetSymbolAddress((void**)&wbph, g_wbph);
    cudaGetSymbolAddress((void**)&wap,  g_wap);

    cudaFuncSetAttribute(edge_mma_kernel,
                         cudaFuncAttributeMaxDynamicSharedMemorySize, SM_TOTAL);

    // ---- edge-index width + counting sort by dst ----
    detect_idx_kernel<<<1, 256>>>((const int*)ei);
    cudaMemsetAsync(deg, 0, (size_t)N * sizeof(int));
    cudaMemsetAsync(cur, 0, (size_t)N * sizeof(int));
    hist_kernel<<<512, 256>>>(ei, E, deg);
    scan_kernel<<<1, 1024>>>(deg, off, N);
    scatter_kernel<<<512, 256>>>(ei, E, off, cur, ssrc, sdst);

    // ---- weight prep ----
    prep_wh_kernel<<<8, 256>>>(w1b, wbph);
    prep_wh_kernel<<<8, 256>>>(w2b, wbph + 2048);
    prep_wh_kernel<<<8, 256>>>(w3b, wbph + 4096);
    prep_wa_kernel<<<64, 256>>>(w2a, wap);
    prep_wa_kernel<<<64, 256>>>(w3a, wap + 16384);

    const int node1_grid = (N + 15) / 16;
    const int nodem_grid = (N + 63) / 64;
    const int edge_grid  = 296;   // 2 CTAs/SM

    // Layer 1 (C = 24, scalar)
    node_kernel<24, 16><<<node1_grid, 128>>>(x, w1a, b1a, A, Bh, X2, N);
    edge_mma_kernel<<<edge_grid, 256, SM_TOTAL>>>((const float4*)A, (const uint4*)Bh,
        ssrc, sdst, wbph, b1b, X2, (int)E);
    // Layer 2 (C = 128, tf32 mma)
    node_mma_kernel<<<nodem_grid, 256>>>(X2, wap, b2a, A, Bh, X4, N);
    edge_mma_kernel<<<edge_grid, 256, SM_TOTAL>>>((const float4*)A, (const uint4*)Bh,
        ssrc, sdst, wbph + 2048, b2b, X4, (int)E);
    // Layer 3 (C = 128, tf32 mma)
    node_mma_kernel<<<nodem_grid, 256>>>(X4, wap + 16384, b3a, A, Bh, X6, N);
    edge_mma_kernel<<<edge_grid, 256, SM_TOTAL>>>((const float4*)A, (const uint4*)Bh,
        ssrc, sdst, wbph + 4096, b3b, X6, (int)E);

    // Pool + final linear
    final_kernel<<<(N + 7) / 8, 256>>>(X2, X4, X6, fw, fb, out, N);
}

// round 17
// speedup vs baseline: 2.6423x; 1.0602x over previous
#include <cuda_runtime.h>
#include <cuda_fp16.h>
#include <math.h>
#include <stdint.h>

#define NN   100000
#define OC   128
#define MAXE 1600000

// ---------------------------------------------------------------------------
// Device scratch
// ---------------------------------------------------------------------------
__device__ __align__(16) float  g_A [(size_t)NN * OC];
__device__ __align__(16) __half g_Bh[(size_t)NN * OC];
__device__ __align__(16) float  g_x2[(size_t)NN * OC];
__device__ __align__(16) float  g_x4[(size_t)NN * OC];
__device__ __align__(16) float  g_x6[(size_t)NN * OC];

__device__ int g_deg[NN];
__device__ int g_off[NN + 1];
__device__ int g_cur[NN];
__device__ int g_ssrc[MAXE];
__device__ int g_sdst[MAXE];
// fp16 edge-W fragments per layer: [wN(2)][kk(8)][p(4)][lane(32)] uint4
__device__ __align__(16) uint4 g_wbph[3][2048];
// tf32 node-W fragments (layers 2,3): [wN(4)][kk(16)][nt(8)][lane(32)] uint2
__device__ __align__(16) uint2 g_wap[2][16384];
__device__ int g_idx64;

// ---------------------------------------------------------------------------
// helpers
// ---------------------------------------------------------------------------
__device__ __forceinline__ uint32_t pack_h2(float lo, float hi) {
    __half2 h = __floats2half2_rn(lo, hi);
    return *(uint32_t*)&h;
}
__device__ __forceinline__ uint32_t f2tf32(float f) {
    uint32_t r;
    asm("cvt.rna.tf32.f32 %0, %1;" : "=r"(r) : "f"(f));
    return r;
}
// relu(a + b) in packed half2
__device__ __forceinline__ uint32_t h2_addrelu(uint32_t a, uint32_t b) {
    __half2 z = __float2half2_rn(0.f);
    __half2 r = __hmax2(__hadd2(*(__half2*)&a, *(__half2*)&b), z);
    return *(uint32_t*)&r;
}

__device__ __forceinline__ void mma_f16(float* d, const uint32_t* a,
                                        uint32_t b0, uint32_t b1) {
    asm volatile(
        "mma.sync.aligned.m16n8k16.row.col.f32.f16.f16.f32 "
        "{%0,%1,%2,%3}, {%4,%5,%6,%7}, {%8,%9}, {%0,%1,%2,%3};"
        : "+f"(d[0]), "+f"(d[1]), "+f"(d[2]), "+f"(d[3])
        : "r"(a[0]), "r"(a[1]), "r"(a[2]), "r"(a[3]), "r"(b0), "r"(b1));
}
__device__ __forceinline__ void mma_tf32(float* d, const uint32_t* a,
                                         uint32_t b0, uint32_t b1) {
    asm volatile(
        "mma.sync.aligned.m16n8k8.row.col.f32.tf32.tf32.f32 "
        "{%0,%1,%2,%3}, {%4,%5,%6,%7}, {%8,%9}, {%0,%1,%2,%3};"
        : "+f"(d[0]), "+f"(d[1]), "+f"(d[2]), "+f"(d[3])
        : "r"(a[0]), "r"(a[1]), "r"(a[2]), "r"(a[3]), "r"(b0), "r"(b1));
}

__device__ __forceinline__ uint32_t smem_u32(const void* p) {
    uint32_t a;
    asm("{ .reg .u64 t; cvta.to.shared.u64 t, %1; cvt.u32.u64 %0, t; }"
        : "=r"(a) : "l"(p));
    return a;
}

#define LDMATRIX_X4(r0, r1, r2, r3, addr) \
    asm volatile("ldmatrix.sync.aligned.m8n8.x4.shared.b16 {%0,%1,%2,%3}, [%4];" \
                 : "=r"(r0), "=r"(r1), "=r"(r2), "=r"(r3) : "r"(addr))

// ---------------------------------------------------------------------------
// Index-width detection (int32 vs int64 edge_index)
// ---------------------------------------------------------------------------
__global__ void detect_idx_kernel(const int* __restrict__ ei)
{
    __shared__ int any;
    if (threadIdx.x == 0) any = 0;
    __syncthreads();
    for (int i = threadIdx.x; i < 2048; i += blockDim.x)
        if (ei[2 * i + 1] != 0) any = 1;
    __syncthreads();
    if (threadIdx.x == 0) g_idx64 = (any == 0) ? 1 : 0;
}

// ---------------------------------------------------------------------------
// Counting sort by dst
// ---------------------------------------------------------------------------
__global__ void hist_kernel(const void* __restrict__ ei, long long E, int* __restrict__ deg)
{
    const int idx64 = g_idx64;
    long long i = (long long)blockIdx.x * blockDim.x + threadIdx.x;
    const long long stride = (long long)gridDim.x * blockDim.x;
    for (; i < E; i += stride) {
        int d = idx64 ? (int)((const long long*)ei)[E + i] : ((const int*)ei)[E + i];
        atomicAdd(&deg[d], 1);
    }
}

// Warp-shuffle scan: 4 barriers per 1024-chunk.
__global__ void scan_kernel(const int* __restrict__ deg, int* __restrict__ off, int n)
{
    const unsigned FULL = 0xffffffffu;
    __shared__ int wsum[32];
    __shared__ int carry_s;
    const int tid  = threadIdx.x;
    const int lane = tid & 31;
    const int wid  = tid >> 5;
    if (tid == 0) carry_s = 0;
    __syncthreads();
    for (int base = 0; base < n; base += 1024) {
        int i = base + tid;
        int v = (i < n) ? deg[i] : 0;
        int s = v;
#pragma unroll
        for (int d = 1; d < 32; d <<= 1) {
            int t = __shfl_up_sync(FULL, s, d);
            if (lane >= d) s += t;
        }
        if (lane == 31) wsum[wid] = s;
        __syncthreads();
        if (wid == 0) {
            int w = wsum[lane];
#pragma unroll
            for (int d = 1; d < 32; d <<= 1) {
                int t = __shfl_up_sync(FULL, w, d);
                if (lane >= d) w += t;
            }
            wsum[lane] = w;
        }
        __syncthreads();
        int carry = carry_s;
        if (i < n) off[i] = carry + (wid ? wsum[wid - 1] : 0) + s - v;
        __syncthreads();
        if (tid == 0) carry_s = carry + wsum[31];
        __syncthreads();
    }
    if (threadIdx.x == 0) off[n] = carry_s;
}

__global__ void scatter_kernel(const void* __restrict__ ei, long long E,
                               const int* __restrict__ off, int* __restrict__ cur,
                               int* __restrict__ ssrc, int* __restrict__ sdst)
{
    const int idx64 = g_idx64;
    long long i = (long long)blockIdx.x * blockDim.x + threadIdx.x;
    const long long stride = (long long)gridDim.x * blockDim.x;
    for (; i < E; i += stride) {
        int s, d;
        if (idx64) { s = (int)((const long long*)ei)[i]; d = (int)((const long long*)ei)[E + i]; }
        else       { s = ((const int*)ei)[i];            d = ((const int*)ei)[E + i]; }
        int p = off[d] + atomicAdd(&cur[d], 1);
        ssrc[p] = s;
        sdst[p] = d;
    }
}

// ---------------------------------------------------------------------------
// Pack wb [K=128][N=128] -> fp16 B fragments for m16n8k16 (edge GEMM)
// ---------------------------------------------------------------------------
__global__ void prep_wh_kernel(const float* __restrict__ wb, uint4* __restrict__ outp)
{
    int idx = blockIdx.x * blockDim.x + threadIdx.x;
    if (idx >= 2048) return;
    int lane = idx & 31;
    int p    = (idx >> 5) & 3;
    int kk   = (idx >> 7) & 7;
    int wN   = idx >> 10;
    int g  = lane >> 2, th = lane & 3;
    int n0 = wN * 64 + p * 16 + g;
    int n1 = n0 + 8;
    int k0 = kk * 16 + 2 * th;
    uint4 v;
    v.x = pack_h2(wb[k0 * 128 + n0],       wb[(k0 + 1) * 128 + n0]);
    v.y = pack_h2(wb[(k0 + 8) * 128 + n0], wb[(k0 + 9) * 128 + n0]);
    v.z = pack_h2(wb[k0 * 128 + n1],       wb[(k0 + 1) * 128 + n1]);
    v.w = pack_h2(wb[(k0 + 8) * 128 + n1], wb[(k0 + 9) * 128 + n1]);
    outp[idx] = v;
}

// ---------------------------------------------------------------------------
// Pack wa [2*128][128] -> tf32 fragments for combined node GEMM (m16n8k8).
// idx = wN*4096 + kk*256 + nt*32 + lane (wN at bit 12)
// ---------------------------------------------------------------------------
__global__ void prep_wa_kernel(const float* __restrict__ wa, uint2* __restrict__ outp)
{
    int idx = blockIdx.x * blockDim.x + threadIdx.x;
    if (idx >= 16384) return;
    int lane = idx & 31;
    int nt   = (idx >> 5) & 7;
    int kk   = (idx >> 8) & 15;
    int wN   = idx >> 12;
    int g = lane >> 2, th = lane & 3;
    int n  = wN * 64 + nt * 8 + g;
    int k0 = kk * 8 + th;
    float w0, w1;
    if (n < 128) {
        w0 = wa[k0 * 128 + n]       - wa[(128 + k0) * 128 + n];
        w1 = wa[(k0 + 4) * 128 + n] - wa[(132 + k0) * 128 + n];
    } else {
        int nn = n - 128;
        w0 = wa[(128 + k0) * 128 + nn];
        w1 = wa[(132 + k0) * 128 + nn];
    }
    outp[idx] = make_uint2(f2tf32(w0), f2tf32(w1));
}

// ---------------------------------------------------------------------------
// Scalar node transform (layer 1 only, C = 24)
// ---------------------------------------------------------------------------
template<int C, int NPB>
__global__ __launch_bounds__(128)
void node_kernel(const float* __restrict__ x,
                 const float* __restrict__ wa,
                 const float* __restrict__ ba,
                 float* __restrict__ A,
                 __half* __restrict__ Bh,
                 float* __restrict__ outz,
                 int n_nodes)
{
    __shared__ float xs[NPB * C];
    const int n0  = blockIdx.x * NPB;
    const int tid = threadIdx.x;

    for (int i = tid; i < NPB * C; i += 128) {
        int nn = i / C, c = i % C;
        int n = n0 + nn;
        xs[i] = (n < n_nodes) ? x[(size_t)n * C + c] : 0.f;
    }
    __syncthreads();

    float a[NPB], b[NPB];
#pragma unroll
    for (int t = 0; t < NPB; t++) { a[t] = 0.f; b[t] = 0.f; }

    const int o = tid;
#pragma unroll 4
    for (int c = 0; c < C; c++) {
        float wtop = wa[(size_t)c       * OC + o];
        float wbot = wa[(size_t)(C + c) * OC + o];
        float wd   = wtop - wbot;
#pragma unroll
        for (int t = 0; t < NPB; t++) {
            float xv = xs[t * C + c];
            a[t] += xv * wd;
            b[t] += xv * wbot;
        }
    }
    float bao = ba[o];
#pragma unroll
    for (int t = 0; t < NPB; t++) {
        int n = n0 + t;
        if (n < n_nodes) {
            size_t idx = (size_t)n * OC + o;
            A[idx]    = a[t] + bao;
            Bh[idx]   = __float2half(b[t]);
            outz[idx] = 0.f;
        }
    }
}

// ---------------------------------------------------------------------------
// Tensor node transform (C = 128 layers), tf32 m16n8k8, 64 nodes x 256 outs.
// ---------------------------------------------------------------------------
#define NXS 132

__global__ __launch_bounds__(256, 2)
void node_mma_kernel(const float* __restrict__ x,
                     const uint2* __restrict__ wap,
                     const float* __restrict__ ba,
                     float* __restrict__ A,
                     __half* __restrict__ Bh,
                     float* __restrict__ outz,
                     int n_nodes)
{
    __shared__ uint32_t xs[64 * NXS];
    const int tid  = threadIdx.x;
    const int wid  = tid >> 5;
    const int lane = tid & 31;
    const int n0   = blockIdx.x * 64;

    for (int i = tid; i < 64 * 32; i += 256) {
        int r = i >> 5, q = i & 31;
        uint4 v;
        if (n0 + r < n_nodes) {
            float4 f = *(const float4*)(x + (size_t)(n0 + r) * 128 + q * 4);
            v.x = f2tf32(f.x); v.y = f2tf32(f.y);
            v.z = f2tf32(f.z); v.w = f2tf32(f.w);
        } else {
            v = make_uint4(0u, 0u, 0u, 0u);
        }
        *(uint4*)(xs + r * NXS + q * 4) = v;
    }
    __syncthreads();

    const int wM = wid & 1;
    const int wN = wid >> 1;
    const int g = lane >> 2, th = lane & 3;

    float acc[2][8][4];
#pragma unroll
    for (int mt = 0; mt < 2; mt++)
#pragma unroll
        for (int nt = 0; nt < 8; nt++)
#pragma unroll
            for (int r = 0; r < 4; r++) acc[mt][nt][r] = 0.f;

    const uint2* wrow = wap + (size_t)wN * 4096 + lane;
#pragma unroll 4
    for (int kk = 0; kk < 16; kk++) {
        uint32_t a[2][4];
#pragma unroll
        for (int mt = 0; mt < 2; mt++) {
            const uint32_t* base = xs + (wM * 32 + mt * 16 + g) * NXS + kk * 8 + th;
            a[mt][0] = base[0];
            a[mt][1] = base[8 * NXS];
            a[mt][2] = base[4];
            a[mt][3] = base[8 * NXS + 4];
        }
#pragma unroll
        for (int nt = 0; nt < 8; nt++) {
            uint2 bp = wrow[(kk * 8 + nt) * 32];
#pragma unroll
            for (int mt = 0; mt < 2; mt++)
                mma_tf32(acc[mt][nt], a[mt], bp.x, bp.y);
        }
    }

#pragma unroll
    for (int mt = 0; mt < 2; mt++) {
        const int row = wM * 32 + mt * 16 + g;
#pragma unroll
        for (int nt = 0; nt < 8; nt++) {
            const int col = wN * 64 + nt * 8 + 2 * th;
            if (wN < 2) {
                float b0 = ba[col], b1 = ba[col + 1];
                int n = n0 + row;
                if (n < n_nodes) {
                    size_t i0 = (size_t)n * OC + col;
                    *(float2*)(A + i0) = make_float2(acc[mt][nt][0] + b0,
                                                     acc[mt][nt][1] + b1);
                    *(float2*)(outz + i0) = make_float2(0.f, 0.f);
                }
                n = n0 + row + 8;
                if (n < n_nodes) {
                    size_t i1 = (size_t)n * OC + col;
                    *(float2*)(A + i1) = make_float2(acc[mt][nt][2] + b0,
                                                     acc[mt][nt][3] + b1);
                    *(float2*)(outz + i1) = make_float2(0.f, 0.f);
                }
            } else {
                const int oc = col - 128;
                int n = n0 + row;
                if (n < n_nodes) {
                    __half2 h = __floats2half2_rn(acc[mt][nt][0], acc[mt][nt][1]);
                    *(__half2*)(Bh + (size_t)n * OC + oc) = h;
                }
                n = n0 + row + 8;
                if (n < n_nodes) {
                    __half2 h = __floats2half2_rn(acc[mt][nt][2], acc[mt][nt][3]);
                    *(__half2*)(Bh + (size_t)n * OC + oc) = h;
                }
            }
        }
    }
}

// ---------------------------------------------------------------------------
// Edge kernel (mma.sync fp16 m16n8k16, sorted edges, 2 CTAs/SM).
// Unique A rows staged once per tile as half2; H-build pure half2.
// msg buffer fp32 (precision-critical); segmented max vectorized float4.
// ---------------------------------------------------------------------------
#define HP   132   // msg row stride (fp32 words)
#define AHW  68    // As_h2 row stride (uint32 half2 words)
#define HHW  68    // H row stride in 32-bit words

#define SM_H     0                          // H 34816; msg (67584) overlays H+As
#define SM_AS    34816                      // 64*68*4 = 17408 (region to 68608)
#define SM_SDST  68608                      // int[128]
#define SM_SSRC  (SM_SDST + 512)
#define SM_ESEG  (SM_SSRC + 512)            // int[128]
#define SM_SEGS  (SM_ESEG + 512)            // int[136]
#define SM_SEGN  (SM_SEGS + 544)
#define SM_BB    (SM_SEGN + 512)
#define SM_WC    (SM_BB + 512)
#define SM_NSEG  (SM_WC + 32)
#define SM_TOTAL (SM_NSEG + 16)             // 71760

__global__ __launch_bounds__(256, 2)
void edge_mma_kernel(const float4* __restrict__ nodeA,
                     const uint4*  __restrict__ nodeBh,
                     const int* __restrict__ ssrc_g,
                     const int* __restrict__ sdst_g,
                     const uint4* __restrict__ wbph,
                     const float* __restrict__ bb,
                     float* __restrict__ out,
                     int E)
{
    extern __shared__ __align__(16) char smem[];
    const int tid  = threadIdx.x;
    const int wid  = tid >> 5;
    const int lane = tid & 31;
    const unsigned FULL = 0xffffffffu;

    uint32_t* Hw   = (uint32_t*)(smem + SM_H);
    uint32_t* Ash  = (uint32_t*)(smem + SM_AS);  // half2 rows
    float*    msg  = (float*)(smem + SM_H);      // fp32 msg, overlays H+As
    int*      sdst = (int*)(smem + SM_SDST);
    int*      ssrc = (int*)(smem + SM_SSRC);
    int*      eseg = (int*)(smem + SM_ESEG);
    int*      segs = (int*)(smem + SM_SEGS);
    int*      segn = (int*)(smem + SM_SEGN);
    float*    bbs  = (float*)(smem + SM_BB);
    int*      swc  = (int*)(smem + SM_WC);
    int*      snseg= (int*)(smem + SM_NSEG);

    if (tid < 128) bbs[tid] = bb[tid];

    const int ntiles = (E + 127) >> 7;
    const int wM = wid & 3;
    const int wN = wid >> 2;

    const int lm_m   = lane >> 3;
    const int lm_row = (lane & 7) + ((lm_m & 1) << 3);
    const int lm_cw  = (lm_m >> 1) * 4;
    uint32_t lm_addr[2];
#pragma unroll
    for (int mt = 0; mt < 2; mt++)
        lm_addr[mt] = smem_u32(Hw + (wM * 32 + mt * 16 + lm_row) * HHW + lm_cw);

    for (int t = blockIdx.x; t < ntiles; t += gridDim.x) {
        const int e0  = t << 7;
        const int cnt = min(128, E - e0);

        if (tid < 128) {
            sdst[tid] = (tid < cnt) ? sdst_g[e0 + tid] : -1;
            ssrc[tid] = (tid < cnt) ? ssrc_g[e0 + tid] : 0;
        }
        __syncthreads();                                          // S1

        int head = 0; unsigned bm = 0;
        if (tid < 128) {
            head = (tid < cnt) && (tid == 0 || sdst[tid] != sdst[tid - 1]);
            bm = __ballot_sync(FULL, head);
            if (lane == 0) swc[wid] = __popc(bm);
        }
        __syncthreads();                                          // S2
        if (tid == 0) {
            int s = 0;
            for (int w = 0; w < 4; w++) { swc[4 + w] = s; s += swc[w]; }
            snseg[0] = s;
            segs[s]  = cnt;
        }
        __syncthreads();                                          // S3
        if (tid < 128) {
            int incl = swc[4 + wid] + __popc(bm << (31 - lane));
            eseg[tid] = incl - 1;
            if (head) { segs[incl - 1] = tid; segn[incl - 1] = sdst[tid]; }
        }
        __syncthreads();                                          // S4

        // stage unique A rows as half2 (convert once per unique row)
        {
            const int nstage = min(snseg[0], 64);
            for (int i = tid; i < (nstage << 4); i += 256) {
                int s = i >> 4, q = i & 15;
                const float4* src = nodeA + (size_t)segn[s] * 32 + q * 2;
                float4 f0 = src[0], f1 = src[1];
                uint4 v;
                v.x = pack_h2(f0.x, f0.y);
                v.y = pack_h2(f0.z, f0.w);
                v.z = pack_h2(f1.x, f1.y);
                v.w = pack_h2(f1.z, f1.w);
                *(uint4*)(Ash + s * AHW + q * 4) = v;
            }
        }
        __syncthreads();                                          // S5

        // H[e][k] = relu_h2(As_h2[seg] + Bh[src])
        {
            const int e    = tid >> 1;
            const int half = tid & 1;
            uint4* hrow = (uint4*)Hw + e * (HHW / 4) + half * 8;
            if (e < cnt) {
                const int sid = eseg[e];
                const uint4* brow = nodeBh + (size_t)ssrc[e] * 16 + half * 8;
                if (sid < 64) {
                    const uint4* arow = (const uint4*)(Ash + sid * AHW) + half * 8;
#pragma unroll
                    for (int m = 0; m < 8; m++) {
                        uint4 av = arow[m];
                        uint4 bv = brow[m];
                        uint4 w;
                        w.x = h2_addrelu(av.x, bv.x);
                        w.y = h2_addrelu(av.y, bv.y);
                        w.z = h2_addrelu(av.z, bv.z);
                        w.w = h2_addrelu(av.w, bv.w);
                        hrow[m] = w;
                    }
                } else {
                    const float4* arow = nodeA + (size_t)sdst[e] * 32 + half * 16;
#pragma unroll
                    for (int m = 0; m < 8; m++) {
                        float4 a0 = arow[2 * m];
                        float4 a1 = arow[2 * m + 1];
                        uint4  bv = brow[m];
                        float2 f0 = __half22float2(*(__half2*)&bv.x);
                        float2 f1 = __half22float2(*(__half2*)&bv.y);
                        float2 f2 = __half22float2(*(__half2*)&bv.z);
                        float2 f3 = __half22float2(*(__half2*)&bv.w);
                        uint4 w;
                        w.x = pack_h2(fmaxf(a0.x + f0.x, 0.f), fmaxf(a0.y + f0.y, 0.f));
                        w.y = pack_h2(fmaxf(a0.z + f1.x, 0.f), fmaxf(a0.w + f1.y, 0.f));
                        w.z = pack_h2(fmaxf(a1.x + f2.x, 0.f), fmaxf(a1.y + f2.y, 0.f));
                        w.w = pack_h2(fmaxf(a1.z + f3.x, 0.f), fmaxf(a1.w + f3.y, 0.f));
                        hrow[m] = w;
                    }
                }
            } else {
#pragma unroll
                for (int m = 0; m < 8; m++)
                    hrow[m] = make_uint4(0u, 0u, 0u, 0u);
            }
        }
        __syncthreads();                                          // S6

        // MMA: warp tile 32 edges x 64 outs
        float acc[2][8][4];
#pragma unroll
        for (int mt = 0; mt < 2; mt++)
#pragma unroll
            for (int nt = 0; nt < 8; nt++)
#pragma unroll
                for (int r = 0; r < 4; r++) acc[mt][nt][r] = 0.f;

        const int g = lane >> 2, th = lane & 3;
        const uint4* wrow = wbph + (size_t)wN * 1024 + lane;
#pragma unroll
        for (int kk = 0; kk < 8; kk++) {
            uint32_t a[2][4];
#pragma unroll
            for (int mt = 0; mt < 2; mt++)
                LDMATRIX_X4(a[mt][0], a[mt][1], a[mt][2], a[mt][3],
                            lm_addr[mt] + kk * 32);
#pragma unroll
            for (int p = 0; p < 4; p++) {
                uint4 bp = wrow[kk * 128 + p * 32];
#pragma unroll
                for (int mt = 0; mt < 2; mt++) {
                    mma_f16(acc[mt][2 * p],     a[mt], bp.x, bp.y);
                    mma_f16(acc[mt][2 * p + 1], a[mt], bp.z, bp.w);
                }
            }
        }
        __syncthreads();                                          // S7

        // store D -> msg[e][c] (fp32, overlays H/As, both dead now)
#pragma unroll
        for (int mt = 0; mt < 2; mt++) {
            const int row = wM * 32 + mt * 16 + g;
#pragma unroll
            for (int nt = 0; nt < 8; nt++) {
                const int col = wN * 64 + nt * 8 + 2 * th;
                *(float2*)(msg + row * HP + col) =
                    make_float2(acc[mt][nt][0], acc[mt][nt][1]);
                *(float2*)(msg + (row + 8) * HP + col) =
                    make_float2(acc[mt][nt][2], acc[mt][nt][3]);
            }
        }
        __syncthreads();                                          // S8

        // segmented max (float4 vectorized: thread owns 4 channels) + writeback
        {
            const int nseg = snseg[0];
            for (int i = tid; i < nseg * 32; i += 256) {
                const int c4 = (i & 31) << 2;
                const int s  = i >> 5;
                const int st = segs[s], en = segs[s + 1];
                float4 m = *(const float4*)(msg + st * HP + c4);
                for (int e = st + 1; e < en; e++) {
                    float4 v = *(const float4*)(msg + e * HP + c4);
                    m.x = fmaxf(m.x, v.x);
                    m.y = fmaxf(m.y, v.y);
                    m.z = fmaxf(m.z, v.z);
                    m.w = fmaxf(m.w, v.w);
                }
                m.x += bbs[c4];
                m.y += bbs[c4 + 1];
                m.z += bbs[c4 + 2];
                m.w += bbs[c4 + 3];
                float* o = out + (size_t)segn[s] * OC + c4;
                if (st == 0 || en == cnt) {
                    atomicMax((int*)o,     __float_as_int(m.x));  // 0-init => relu free
                    atomicMax((int*)o + 1, __float_as_int(m.y));
                    atomicMax((int*)o + 2, __float_as_int(m.z));
                    atomicMax((int*)o + 3, __float_as_int(m.w));
                } else {
                    *(float4*)o = make_float4(fmaxf(m.x, 0.f), fmaxf(m.y, 0.f),
                                              fmaxf(m.z, 0.f), fmaxf(m.w, 0.f));
                }
            }
        }
        __syncthreads();                                          // S9
    }
}

// ---------------------------------------------------------------------------
// Final: concat(x2,x4,x6) [384] -> maxpool(24) -> 16 -> @ fw + fb
// ---------------------------------------------------------------------------
__global__ __launch_bounds__(256)
void final_kernel(const float* __restrict__ x2,
                  const float* __restrict__ x4,
                  const float* __restrict__ x6,
                  const float* __restrict__ fw,
                  const float* __restrict__ fb,
                  float* __restrict__ out,
                  int n_nodes)
{
    const unsigned FULL = 0xffffffffu;
    const int lane = threadIdx.x & 31;
    const int warp = blockIdx.x * (blockDim.x >> 5) + (threadIdx.x >> 5);
    const int nw   = gridDim.x * (blockDim.x >> 5);

    for (int n = warp; n < n_nodes; n += nw) {
        float m = -3.4e38f;
        int idx0 = lane * 12;
#pragma unroll
        for (int i = 0; i < 12; i++) {
            int idx = idx0 + i;
            float v;
            if (idx < 128)       v = x2[(size_t)n * OC + idx];
            else if (idx < 256)  v = x4[(size_t)n * OC + idx - 128];
            else                 v = x6[(size_t)n * OC + idx - 256];
            m = fmaxf(m, v);
        }
        float mm = fmaxf(m, __shfl_xor_sync(FULL, m, 1));
        float part = ((lane & 1) == 0) ? mm * fw[lane >> 1] : 0.f;
#pragma unroll
        for (int off = 16; off >= 1; off >>= 1)
            part += __shfl_xor_sync(FULL, part, off);
        if (lane == 0) out[n] = part + fb[0];
    }
}

// ---------------------------------------------------------------------------
extern "C" void kernel_launch(void* const* d_in, const int* in_sizes, int n_in,
                              void* d_out, int out_size)
{
    const float* x   = (const float*)d_in[0];
    const void*  ei  = d_in[1];
    const float* w1a = (const float*)d_in[2];  const float* b1a = (const float*)d_in[3];
    const float* w1b = (const float*)d_in[4];  const float* b1b = (const float*)d_in[5];
    const float* w2a = (const float*)d_in[6];  const float* b2a = (const float*)d_in[7];
    const float* w2b = (const float*)d_in[8];  const float* b2b = (const float*)d_in[9];
    const float* w3a = (const float*)d_in[10]; const float* b3a = (const float*)d_in[11];
    const float* w3b = (const float*)d_in[12]; const float* b3b = (const float*)d_in[13];
    const float* fw  = (const float*)d_in[14]; const float* fb  = (const float*)d_in[15];
    float* out = (float*)d_out;

    const int       N = in_sizes[0] / 24;
    const long long E = in_sizes[1] / 2;

    float *A, *X2, *X4, *X6;
    __half *Bh;
    int *deg, *off, *cur, *ssrc, *sdst;
    uint4 *wbph;
    uint2 *wap;
    cudaGetSymbolAddress((void**)&A,    g_A);
    cudaGetSymbolAddress((void**)&Bh,   g_Bh);
    cudaGetSymbolAddress((void**)&X2,   g_x2);
    cudaGetSymbolAddress((void**)&X4,   g_x4);
    cudaGetSymbolAddress((void**)&X6,   g_x6);
    cudaGetSymbolAddress((void**)&deg,  g_deg);
    cudaGetSymbolAddress((void**)&off,  g_off);
    cudaGetSymbolAddress((void**)&cur,  g_cur);
    cudaGetSymbolAddress((void**)&ssrc, g_ssrc);
    cudaGetSymbolAddress((void**)&sdst, g_sdst);
    cudaGetSymbolAddress((void**)&wbph, g_wbph);
    cudaGetSymbolAddress((void**)&wap,  g_wap);

    cudaFuncSetAttribute(edge_mma_kernel,
                         cudaFuncAttributeMaxDynamicSharedMemorySize, SM_TOTAL);

    // ---- edge-index width + counting sort by dst ----
    detect_idx_kernel<<<1, 256>>>((const int*)ei);
    cudaMemsetAsync(deg, 0, (size_t)N * sizeof(int));
    cudaMemsetAsync(cur, 0, (size_t)N * sizeof(int));
    hist_kernel<<<512, 256>>>(ei, E, deg);
    scan_kernel<<<1, 1024>>>(deg, off, N);
    scatter_kernel<<<512, 256>>>(ei, E, off, cur, ssrc, sdst);

    // ---- weight prep ----
    prep_wh_kernel<<<8, 256>>>(w1b, wbph);
    prep_wh_kernel<<<8, 256>>>(w2b, wbph + 2048);
    prep_wh_kernel<<<8, 256>>>(w3b, wbph + 4096);
    prep_wa_kernel<<<64, 256>>>(w2a, wap);
    prep_wa_kernel<<<64, 256>>>(w3a, wap + 16384);

    const int node1_grid = (N + 15) / 16;
    const int nodem_grid = (N + 63) / 64;
    const int edge_grid  = 296;   // 2 CTAs/SM

    // Layer 1 (C = 24, scalar)
    node_kernel<24, 16><<<node1_grid, 128>>>(x, w1a, b1a, A, Bh, X2, N);
    edge_mma_kernel<<<edge_grid, 256, SM_TOTAL>>>((const float4*)A, (const uint4*)Bh,
        ssrc, sdst, wbph, b1b, X2, (int)E);
    // Layer 2 (C = 128, tf32 mma)
    node_mma_kernel<<<nodem_grid, 256>>>(X2, wap, b2a, A, Bh, X4, N);
    edge_mma_kernel<<<edge_grid, 256, SM_TOTAL>>>((const float4*)A, (const uint4*)Bh,
        ssrc, sdst, wbph + 2048, b2b, X4, (int)E);
    // Layer 3 (C = 128, tf32 mma)
    node_mma_kernel<<<nodem_grid, 256>>>(X4, wap + 16384, b3a, A, Bh, X6, N);
    edge_mma_kernel<<<edge_grid, 256, SM_TOTAL>>>((const float4*)A, (const uint4*)Bh,
        ssrc, sdst, wbph + 4096, b3b, X6, (int)E);

    // Pool + final linear
    final_kernel<<<(N + 7) / 8, 256>>>(X2, X4, X6, fw, fb, out, N);
}